// round 3
// baseline (speedup 1.0000x reference)
#include <cuda_runtime.h>
#include <cstdint>
#include <cstddef>

#define B_    32
#define T1_   512
#define T2_   2048
#define CENC  512
#define HCH   80
#define SLOPE_ 0.3f
#define TEMP_  0.0005f
#define NEGV  -1000000000.0f

__device__ float g_K1[B_*HCH*T1_];
__device__ float g_K [B_*HCH*T1_];
__device__ float g_QA[B_*HCH*T2_];
__device__ float g_QB[B_*HCH*T2_];
__device__ float g_k2[B_*T1_];
__device__ float g_q2[B_*T2_];
__device__ float g_lpT[(size_t)B_*T2_*T1_];   // log-prior^T, then reused for log(attn_soft)

__global__ void __launch_bounds__(256) transpose_logprior(
        const float* __restrict__ prior, float* __restrict__ lpT)
{
    __shared__ float tile[32][33];
    const int b = blockIdx.z;
    const int t1_0 = blockIdx.x * 32, t2_0 = blockIdx.y * 32;
    const int tx = threadIdx.x, ty = threadIdx.y;
#pragma unroll
    for (int i = 0; i < 4; i++)
        tile[ty + 8*i][tx] = prior[((size_t)b*T1_ + t1_0 + ty + 8*i)*T2_ + t2_0 + tx];
    __syncthreads();
#pragma unroll
    for (int i = 0; i < 4; i++)
        lpT[((size_t)b*T2_ + t2_0 + ty + 8*i)*T1_ + t1_0 + tx] =
            logf(tile[tx][ty + 8*i] + 1e-8f);
}

template<int CIN, int KSZ, int PAD, int TLEN>
__global__ void __launch_bounds__(256) conv_lrelu(
        const float* __restrict__ x, const float* __restrict__ w,
        const float* __restrict__ bias, float* __restrict__ y)
{
    constexpr int TT  = 128;
    constexpr int CB  = 16;
    constexpr int TIN = TT + KSZ - 1;
    __shared__ float sIn[CB][TIN];
    __shared__ float sW[HCH * CB * KSZ];

    const int b   = blockIdx.y;
    const int t0  = blockIdx.x * TT;
    const int tid = threadIdx.x;
    const int tg  = tid & 15;
    const int og  = tid >> 4;

    float acc[5][8];
#pragma unroll
    for (int i = 0; i < 5; i++)
#pragma unroll
        for (int j = 0; j < 8; j++) acc[i][j] = 0.f;

    for (int c0 = 0; c0 < CIN; c0 += CB) {
        for (int idx = tid; idx < CB*TIN; idx += 256) {
            int ci = idx / TIN, tt = idx - ci*TIN;
            int t = t0 + tt - PAD;
            float v = 0.f;
            if (t >= 0 && t < TLEN) v = x[((size_t)b*CIN + c0 + ci)*TLEN + t];
            sIn[ci][tt] = v;
        }
        for (int idx = tid; idx < HCH*CB*KSZ; idx += 256) {
            int oc  = idx / (CB*KSZ);
            int rem = idx - oc*(CB*KSZ);
            sW[idx] = w[(size_t)oc*CIN*KSZ + c0*KSZ + rem];
        }
        __syncthreads();
#pragma unroll 2
        for (int ci = 0; ci < CB; ci++) {
#pragma unroll
            for (int kk = 0; kk < KSZ; kk++) {
                float iv[8];
#pragma unroll
                for (int j = 0; j < 8; j++) iv[j] = sIn[ci][tg + 16*j + kk];
#pragma unroll
                for (int i = 0; i < 5; i++) {
                    float wv = sW[((og*5 + i)*CB + ci)*KSZ + kk];
#pragma unroll
                    for (int j = 0; j < 8; j++) acc[i][j] = fmaf(wv, iv[j], acc[i][j]);
                }
            }
        }
        __syncthreads();
    }
#pragma unroll
    for (int i = 0; i < 5; i++) {
        int oc = og*5 + i;
        float bv = bias[oc];
#pragma unroll
        for (int j = 0; j < 8; j++) {
            float v = acc[i][j] + bv;
            v = v >= 0.f ? v : SLOPE_ * v;
            y[((size_t)b*HCH + oc)*TLEN + t0 + tg + 16*j] = v;
        }
    }
}

template<int C, int T>
__global__ void __launch_bounds__(256) sumsq_kernel(
        const float* __restrict__ x, float* __restrict__ out)
{
    int idx = blockIdx.x * 256 + threadIdx.x;
    int b = idx / T, t = idx - b*T;
    float s = 0.f;
#pragma unroll 8
    for (int c = 0; c < C; c++) {
        float v = x[((size_t)b*C + c)*T + t];
        s = fmaf(v, v, s);
    }
    out[idx] = s;
}

__global__ void __launch_bounds__(256) attn_raw_kernel(
        const float* __restrict__ Q, const float* __restrict__ K,
        const float* __restrict__ q2s, const float* __restrict__ k2s,
        float* __restrict__ outp)
{
    constexpr int CB = 8;
    __shared__ float sK[CB][T1_];
    __shared__ float sQ[CB][32];
    const int b    = blockIdx.y;
    const int t2_0 = blockIdx.x * 32;
    const int tid  = threadIdx.x;
    const int t1g  = tid & 63;
    const int t2g  = tid >> 6;

    float acc[8][8];
#pragma unroll
    for (int r = 0; r < 8; r++)
#pragma unroll
        for (int j = 0; j < 8; j++) acc[r][j] = 0.f;

    for (int c0 = 0; c0 < HCH; c0 += CB) {
        for (int idx = tid; idx < CB*T1_; idx += 256) {
            int cc = idx >> 9, t1 = idx & 511;
            sK[cc][t1] = K[((size_t)b*HCH + c0 + cc)*T1_ + t1];
        }
        {
            int cc = tid >> 5, r = tid & 31;
            sQ[cc][r] = Q[((size_t)b*HCH + c0 + cc)*T2_ + t2_0 + r];
        }
        __syncthreads();
#pragma unroll
        for (int cc = 0; cc < CB; cc++) {
            float kv[8], qv[8];
#pragma unroll
            for (int j = 0; j < 8; j++) kv[j] = sK[cc][t1g*8 + j];
#pragma unroll
            for (int r = 0; r < 8; r++) qv[r] = sQ[cc][t2g*8 + r];
#pragma unroll
            for (int r = 0; r < 8; r++)
#pragma unroll
                for (int j = 0; j < 8; j++)
                    acc[r][j] = fmaf(qv[r], kv[j], acc[r][j]);
        }
        __syncthreads();
    }
    float k2v[8];
#pragma unroll
    for (int j = 0; j < 8; j++) k2v[j] = k2s[b*T1_ + t1g*8 + j];
#pragma unroll
    for (int r = 0; r < 8; r++) {
        int t2 = t2_0 + t2g*8 + r;
        float q2v = q2s[b*T2_ + t2];
        size_t o = ((size_t)b*T2_ + t2)*T1_ + t1g*8;
        float4 w0, w1;
        w0.x = TEMP_*(2.f*acc[r][0] - q2v - k2v[0]);
        w0.y = TEMP_*(2.f*acc[r][1] - q2v - k2v[1]);
        w0.z = TEMP_*(2.f*acc[r][2] - q2v - k2v[2]);
        w0.w = TEMP_*(2.f*acc[r][3] - q2v - k2v[3]);
        w1.x = TEMP_*(2.f*acc[r][4] - q2v - k2v[4]);
        w1.y = TEMP_*(2.f*acc[r][5] - q2v - k2v[5]);
        w1.z = TEMP_*(2.f*acc[r][6] - q2v - k2v[6]);
        w1.w = TEMP_*(2.f*acc[r][7] - q2v - k2v[7]);
        *(float4*)(outp + o)     = w0;
        *(float4*)(outp + o + 4) = w1;
    }
}

__device__ __forceinline__ float blkMax(float v, float* sh) {
#pragma unroll
    for (int o = 16; o; o >>= 1) v = fmaxf(v, __shfl_xor_sync(0xffffffffu, v, o));
    if ((threadIdx.x & 31) == 0) sh[threadIdx.x >> 5] = v;
    __syncthreads();
    float r = sh[0];
#pragma unroll
    for (int i = 1; i < 8; i++) r = fmaxf(r, sh[i]);
    __syncthreads();
    return r;
}
__device__ __forceinline__ float blkSum(float v, float* sh) {
#pragma unroll
    for (int o = 16; o; o >>= 1) v += __shfl_xor_sync(0xffffffffu, v, o);
    if ((threadIdx.x & 31) == 0) sh[threadIdx.x >> 5] = v;
    __syncthreads();
    float r = sh[0];
#pragma unroll
    for (int i = 1; i < 8; i++) r += sh[i];
    __syncthreads();
    return r;
}

// Reads raw logits from lp and log-prior^T from lpT.
// Writes: lp   <- attn_logprob  (output 0 region)
//         soft <- attn_soft     (output 1 region)
//         lpT  <- log(attn_soft)  (scratch reuse, consumed by MAS)
__global__ void __launch_bounds__(256) rowsoft_kernel(
        float* __restrict__ lp, float* __restrict__ lpT,
        float* __restrict__ soft)
{
    __shared__ float sh[8];
    const size_t off = (size_t)blockIdx.x * T1_;
    const int tid = threadIdx.x;
    float v0 = lp[off + tid], v1 = lp[off + 256 + tid];
    float m  = blkMax(fmaxf(v0, v1), sh);
    float s  = blkSum(expf(v0 - m) + expf(v1 - m), sh);
    float lse = m + logf(s);
    float a0 = v0 - lse + lpT[off + tid];
    float a1 = v1 - lse + lpT[off + 256 + tid];
    float m2 = blkMax(fmaxf(a0, a1), sh);
    float p0 = expf(a0 - m2), p1 = expf(a1 - m2);
    float s2 = blkSum(p0 + p1, sh);
    float inv = 1.0f / s2;
    float sm0 = p0 * inv, sm1 = p1 * inv;
    lp[off + tid] = a0;            lp[off + 256 + tid] = a1;
    soft[off + tid] = sm0;         soft[off + 256 + tid] = sm1;
    lpT[off + tid] = logf(sm0);    lpT[off + 256 + tid] = logf(sm1);
}

__global__ void zero_kernel(float4* __restrict__ p) {
    size_t i = (size_t)blockIdx.x * blockDim.x + threadIdx.x;
    p[i] = make_float4(0.f, 0.f, 0.f, 0.f);
}

#define MAS_RING 8
#define MAS_SMEM (T2_*32*2 + T1_*4)

__global__ void __launch_bounds__(32) mas_kernel(
        const float* __restrict__ la, const int* __restrict__ enc_len,
        const int* __restrict__ dec_len, float* __restrict__ hard,
        float* __restrict__ dur)
{
    extern __shared__ unsigned short sBits[];
    int* durS = (int*)&sBits[T2_*32];
    const int b = blockIdx.x;
    const int lane = threadIdx.x;
    const int el = enc_len[b];
    const int dl = dec_len[b];
    const float* rowbase = la + (size_t)b*T2_*T1_ + lane*16;

    unsigned validbits = 0u;
    float logp[16];
#pragma unroll
    for (int k = 0; k < 16; k++) {
        logp[k] = (lane == 0 && k == 0) ? 0.f : NEGV;
        if (lane*16 + k < el) validbits |= (1u << k);
    }
    float4 ring[MAS_RING][4];
#pragma unroll
    for (int p = 0; p < MAS_RING; p++)
#pragma unroll
        for (int q = 0; q < 4; q++)
            ring[p][q] = *(const float4*)(rowbase + (size_t)p*T1_ + q*4);

    for (int t2b = 0; t2b < T2_; t2b += MAS_RING) {
#pragma unroll
        for (int u = 0; u < MAS_RING; u++) {
            const int t2 = t2b + u;
            float rv[16];
            rv[0]=ring[u][0].x;  rv[1]=ring[u][0].y;  rv[2]=ring[u][0].z;  rv[3]=ring[u][0].w;
            rv[4]=ring[u][1].x;  rv[5]=ring[u][1].y;  rv[6]=ring[u][1].z;  rv[7]=ring[u][1].w;
            rv[8]=ring[u][2].x;  rv[9]=ring[u][2].y;  rv[10]=ring[u][2].z; rv[11]=ring[u][2].w;
            rv[12]=ring[u][3].x; rv[13]=ring[u][3].y; rv[14]=ring[u][3].z; rv[15]=ring[u][3].w;
            const int tn = t2 + MAS_RING;
            if (tn < T2_) {
#pragma unroll
                for (int q = 0; q < 4; q++)
                    ring[u][q] = *(const float4*)(rowbase + (size_t)tn*T1_ + q*4);
            }
#pragma unroll
            for (int k = 0; k < 16; k++)
                rv[k] = ((validbits >> k) & 1u) ? rv[k] : NEGV;
            if (t2 == 0) {
#pragma unroll
                for (int k = 0; k < 16; k++)
                    if (lane > 0 || k > 0) rv[k] = NEGV;
            }
            float last = __shfl_up_sync(0xffffffffu, logp[15], 1);
            unsigned bits = 0u;
#pragma unroll
            for (int k = 15; k >= 0; k--) {
                float sh = (k == 0) ? last : logp[k-1];
                bool t1pos = (k > 0) || (lane > 0);
                bool take = t1pos && (sh >= logp[k]);
                float base = take ? sh : logp[k];
                if (take) bits |= (1u << k);
                logp[k] = rv[k] + base;
            }
            sBits[t2*32 + lane] = (unsigned short)bits;
        }
    }
    __syncwarp();
    for (int i = lane; i < T1_; i += 32) durS[i] = 0;
    __syncwarp();
    if (lane == 0) {
        int curr = el - 1;
        for (int i = T2_-1; i >= 0; --i) {
            if (i < dl) {
                hard[((size_t)b*T2_ + i)*T1_ + curr] = 1.0f;
                durS[curr]++;
                unsigned bits = sBits[i*32 + (curr >> 4)];
                curr -= (int)((bits >> (curr & 15)) & 1u);
            }
        }
    }
    __syncwarp();
    for (int i = lane; i < T1_; i += 32) dur[(size_t)b*T1_ + i] = (float)durS[i];
}

extern "C" void kernel_launch(void* const* d_in, const int* in_sizes, int n_in,
                              void* d_out, int out_size)
{
    const float* enc_in  = (const float*)d_in[0];
    const float* dec_in  = (const float*)d_in[1];
    const int*   enc_len = (const int*)d_in[2];
    const int*   dec_len = (const int*)d_in[3];
    const float* prior   = (const float*)d_in[5];
    const float* kw1 = (const float*)d_in[6];
    const float* kb1 = (const float*)d_in[7];
    const float* kw2 = (const float*)d_in[8];
    const float* kb2 = (const float*)d_in[9];
    const float* qw1 = (const float*)d_in[10];
    const float* qb1 = (const float*)d_in[11];
    const float* qw2 = (const float*)d_in[12];
    const float* qb2 = (const float*)d_in[13];
    const float* qw3 = (const float*)d_in[14];
    const float* qb3 = (const float*)d_in[15];

    float* outp = (float*)d_out;
    const size_t VOL = (size_t)B_*T2_*T1_;
    float* lp   = outp;
    float* soft = outp + VOL;
    float* hard = outp + 2*VOL;
    float* dur  = outp + 3*VOL;

    float *pK1, *pK, *pQA, *pQB, *pk2, *pq2, *plpT;
    cudaGetSymbolAddress((void**)&pK1,  g_K1);
    cudaGetSymbolAddress((void**)&pK,   g_K);
    cudaGetSymbolAddress((void**)&pQA,  g_QA);
    cudaGetSymbolAddress((void**)&pQB,  g_QB);
    cudaGetSymbolAddress((void**)&pk2,  g_k2);
    cudaGetSymbolAddress((void**)&pq2,  g_q2);
    cudaGetSymbolAddress((void**)&plpT, g_lpT);

    transpose_logprior<<<dim3(T1_/32, T2_/32, B_), dim3(32, 8)>>>(prior, plpT);

    conv_lrelu<CENC, 3, 1, T1_><<<dim3(T1_/128, B_), 256>>>(enc_in, kw1, kb1, pK1);
    conv_lrelu<HCH,  3, 1, T1_><<<dim3(T1_/128, B_), 256>>>(pK1,    kw2, kb2, pK);
    conv_lrelu<HCH,  7, 3, T2_><<<dim3(T2_/128, B_), 256>>>(dec_in, qw1, qb1, pQA);
    conv_lrelu<HCH,  7, 3, T2_><<<dim3(T2_/128, B_), 256>>>(pQA,    qw2, qb2, pQB);
    conv_lrelu<HCH,  7, 3, T2_><<<dim3(T2_/128, B_), 256>>>(pQB,    qw3, qb3, pQA);

    sumsq_kernel<HCH, T1_><<<B_*T1_/256, 256>>>(pK,  pk2);
    sumsq_kernel<HCH, T2_><<<B_*T2_/256, 256>>>(pQA, pq2);

    attn_raw_kernel<<<dim3(T2_/32, B_), 256>>>(pQA, pK, pq2, pk2, lp);
    rowsoft_kernel<<<B_*T2_, 256>>>(lp, plpT, soft);

    zero_kernel<<<(unsigned)(VOL/4/256), 256>>>((float4*)hard);

    static int smem_set = 0;
    if (!smem_set) {
        cudaFuncSetAttribute(mas_kernel, cudaFuncAttributeMaxDynamicSharedMemorySize, MAS_SMEM);
        smem_set = 1;
    }
    mas_kernel<<<B_, 32, MAS_SMEM>>>(plpT, enc_len, dec_len, hard, dur);
}

// round 4
// speedup vs baseline: 1.0047x; 1.0047x over previous
#include <cuda_runtime.h>
#include <cstdint>
#include <cstddef>

#define B_    32
#define T1_   512
#define T2_   2048
#define CENC  512
#define HCH   80
#define SLOPE_ 0.3f
#define TEMP_  0.0005f
#define NEGV  -1000000000.0f

__device__ float g_K1[B_*HCH*T1_];
__device__ float g_K [B_*HCH*T1_];
__device__ float g_QA[B_*HCH*T2_];
__device__ float g_QB[B_*HCH*T2_];
__device__ float g_k2[B_*T1_];
__device__ float g_q2[B_*T2_];
__device__ float g_lpT[(size_t)B_*T2_*T1_];   // log-prior^T, then reused for log(attn_soft)

__global__ void __launch_bounds__(256) transpose_logprior(
        const float* __restrict__ prior, float* __restrict__ lpT)
{
    __shared__ float tile[32][33];
    const int b = blockIdx.z;
    const int t1_0 = blockIdx.x * 32, t2_0 = blockIdx.y * 32;
    const int tx = threadIdx.x, ty = threadIdx.y;
#pragma unroll
    for (int i = 0; i < 4; i++)
        tile[ty + 8*i][tx] = prior[((size_t)b*T1_ + t1_0 + ty + 8*i)*T2_ + t2_0 + tx];
    __syncthreads();
#pragma unroll
    for (int i = 0; i < 4; i++)
        lpT[((size_t)b*T2_ + t2_0 + ty + 8*i)*T1_ + t1_0 + tx] =
            logf(tile[tx][ty + 8*i] + 1e-8f);
}

// Conv1d + leaky relu. Thread owns 5 oc x 8 contiguous t.
// Register sliding window: 16-float window loaded as 4x LDS.128 per ci.
template<int CIN, int KSZ, int PAD, int TLEN>
__global__ void __launch_bounds__(128) conv_lrelu(
        const float* __restrict__ x, const float* __restrict__ wgt,
        const float* __restrict__ bias, float* __restrict__ y)
{
    constexpr int TT  = 64;
    constexpr int CB  = 16;
    constexpr int INW = TT + 8;              // 4-float lead pad + TT + 4 tail
    constexpr int WSLOT = (KSZ <= 4) ? 4 : 8;
    constexpr int OFF = 4 - PAD;             // tap index offset into window
    __shared__ float sIn[CB][INW];
    __shared__ float sW[CB*HCH*WSLOT];

    const int b   = blockIdx.y;
    const int t0  = blockIdx.x * TT;
    const int tid = threadIdx.x;
    const int tg  = tid & 7;                 // 8 t-groups of 8 contiguous t
    const int og  = tid >> 3;                // 16 oc-groups of 5 oc

    float acc[5][8];
#pragma unroll
    for (int i = 0; i < 5; i++)
#pragma unroll
        for (int j = 0; j < 8; j++) acc[i][j] = 0.f;

    for (int c0 = 0; c0 < CIN; c0 += CB) {
        for (int idx = tid; idx < CB*INW; idx += 128) {
            int ci = idx / INW, u = idx - ci*INW;
            int t = t0 + u - 4;
            sIn[ci][u] = ((unsigned)t < (unsigned)TLEN)
                       ? x[((size_t)b*CIN + c0 + ci)*TLEN + t] : 0.f;
        }
        for (int idx = tid; idx < CB*HCH*KSZ; idx += 128) {
            int ci  = idx / (HCH*KSZ);
            int rem = idx - ci*(HCH*KSZ);
            int oc  = rem / KSZ;
            int k   = rem - oc*KSZ;
            sW[(ci*HCH + oc)*WSLOT + k] =
                wgt[(size_t)oc*CIN*KSZ + (size_t)(c0 + ci)*KSZ + k];
        }
        __syncthreads();
#pragma unroll 1
        for (int ci = 0; ci < CB; ci++) {
            float wreg[16];
            float4 a0 = *(const float4*)&sIn[ci][tg*8 + 0];
            float4 a1 = *(const float4*)&sIn[ci][tg*8 + 4];
            float4 a2 = *(const float4*)&sIn[ci][tg*8 + 8];
            float4 a3 = *(const float4*)&sIn[ci][tg*8 + 12];
            wreg[0]=a0.x; wreg[1]=a0.y; wreg[2]=a0.z; wreg[3]=a0.w;
            wreg[4]=a1.x; wreg[5]=a1.y; wreg[6]=a1.z; wreg[7]=a1.w;
            wreg[8]=a2.x; wreg[9]=a2.y; wreg[10]=a2.z; wreg[11]=a2.w;
            wreg[12]=a3.x; wreg[13]=a3.y; wreg[14]=a3.z; wreg[15]=a3.w;
#pragma unroll
            for (int i = 0; i < 5; i++) {
                const float* wp = &sW[(ci*HCH + og*5 + i)*WSLOT];
                float wf[WSLOT];
                float4 b0 = *(const float4*)wp;
                wf[0]=b0.x; wf[1]=b0.y; wf[2]=b0.z; wf[3]=b0.w;
                if (WSLOT == 8) {
                    float4 b1 = *(const float4*)(wp + 4);
                    wf[4]=b1.x; wf[5]=b1.y; wf[6]=b1.z; wf[7]=b1.w;
                }
#pragma unroll
                for (int kk = 0; kk < KSZ; kk++)
#pragma unroll
                    for (int j = 0; j < 8; j++)
                        acc[i][j] = fmaf(wf[kk], wreg[j + kk + OFF], acc[i][j]);
            }
        }
        __syncthreads();
    }
#pragma unroll
    for (int i = 0; i < 5; i++) {
        int oc = og*5 + i;
        float bv = bias[oc];
        float4 o0, o1;
        float v;
        v = acc[i][0] + bv; o0.x = v >= 0.f ? v : SLOPE_*v;
        v = acc[i][1] + bv; o0.y = v >= 0.f ? v : SLOPE_*v;
        v = acc[i][2] + bv; o0.z = v >= 0.f ? v : SLOPE_*v;
        v = acc[i][3] + bv; o0.w = v >= 0.f ? v : SLOPE_*v;
        v = acc[i][4] + bv; o1.x = v >= 0.f ? v : SLOPE_*v;
        v = acc[i][5] + bv; o1.y = v >= 0.f ? v : SLOPE_*v;
        v = acc[i][6] + bv; o1.z = v >= 0.f ? v : SLOPE_*v;
        v = acc[i][7] + bv; o1.w = v >= 0.f ? v : SLOPE_*v;
        float* yp = &y[((size_t)b*HCH + oc)*TLEN + t0 + tg*8];
        *(float4*)yp       = o0;
        *(float4*)(yp + 4) = o1;
    }
}

template<int C, int T>
__global__ void __launch_bounds__(256) sumsq_kernel(
        const float* __restrict__ x, float* __restrict__ out)
{
    int idx = blockIdx.x * 256 + threadIdx.x;
    int b = idx / T, t = idx - b*T;
    float s = 0.f;
#pragma unroll 8
    for (int c = 0; c < C; c++) {
        float v = x[((size_t)b*C + c)*T + t];
        s = fmaf(v, v, s);
    }
    out[idx] = s;
}

__global__ void __launch_bounds__(256) attn_raw_kernel(
        const float* __restrict__ Q, const float* __restrict__ K,
        const float* __restrict__ q2s, const float* __restrict__ k2s,
        float* __restrict__ outp)
{
    constexpr int CB = 8;
    __shared__ float sK[CB][T1_];
    __shared__ float sQ[CB][32];
    const int b    = blockIdx.y;
    const int t2_0 = blockIdx.x * 32;
    const int tid  = threadIdx.x;
    const int t1g  = tid & 63;
    const int t2g  = tid >> 6;

    float acc[8][8];
#pragma unroll
    for (int r = 0; r < 8; r++)
#pragma unroll
        for (int j = 0; j < 8; j++) acc[r][j] = 0.f;

    for (int c0 = 0; c0 < HCH; c0 += CB) {
        for (int idx = tid; idx < CB*(T1_/4); idx += 256) {
            int cc = idx >> 7, t4 = idx & 127;
            *(float4*)&sK[cc][t4*4] =
                *(const float4*)&K[((size_t)b*HCH + c0 + cc)*T1_ + t4*4];
        }
        {
            int cc = tid >> 5, r = tid & 31;
            sQ[cc][r] = Q[((size_t)b*HCH + c0 + cc)*T2_ + t2_0 + r];
        }
        __syncthreads();
#pragma unroll
        for (int cc = 0; cc < CB; cc++) {
            float kv[8], qv[8];
            float4 k0 = *(const float4*)&sK[cc][t1g*8];
            float4 k1 = *(const float4*)&sK[cc][t1g*8 + 4];
            kv[0]=k0.x; kv[1]=k0.y; kv[2]=k0.z; kv[3]=k0.w;
            kv[4]=k1.x; kv[5]=k1.y; kv[6]=k1.z; kv[7]=k1.w;
            float4 q0 = *(const float4*)&sQ[cc][t2g*8];
            float4 q1 = *(const float4*)&sQ[cc][t2g*8 + 4];
            qv[0]=q0.x; qv[1]=q0.y; qv[2]=q0.z; qv[3]=q0.w;
            qv[4]=q1.x; qv[5]=q1.y; qv[6]=q1.z; qv[7]=q1.w;
#pragma unroll
            for (int r = 0; r < 8; r++)
#pragma unroll
                for (int j = 0; j < 8; j++)
                    acc[r][j] = fmaf(qv[r], kv[j], acc[r][j]);
        }
        __syncthreads();
    }
    float k2v[8];
#pragma unroll
    for (int j = 0; j < 8; j++) k2v[j] = k2s[b*T1_ + t1g*8 + j];
#pragma unroll
    for (int r = 0; r < 8; r++) {
        int t2 = t2_0 + t2g*8 + r;
        float q2v = q2s[b*T2_ + t2];
        size_t o = ((size_t)b*T2_ + t2)*T1_ + t1g*8;
        float4 w0, w1;
        w0.x = TEMP_*(2.f*acc[r][0] - q2v - k2v[0]);
        w0.y = TEMP_*(2.f*acc[r][1] - q2v - k2v[1]);
        w0.z = TEMP_*(2.f*acc[r][2] - q2v - k2v[2]);
        w0.w = TEMP_*(2.f*acc[r][3] - q2v - k2v[3]);
        w1.x = TEMP_*(2.f*acc[r][4] - q2v - k2v[4]);
        w1.y = TEMP_*(2.f*acc[r][5] - q2v - k2v[5]);
        w1.z = TEMP_*(2.f*acc[r][6] - q2v - k2v[6]);
        w1.w = TEMP_*(2.f*acc[r][7] - q2v - k2v[7]);
        *(float4*)(outp + o)     = w0;
        *(float4*)(outp + o + 4) = w1;
    }
}

__device__ __forceinline__ float blkMax(float v, float* sh) {
#pragma unroll
    for (int o = 16; o; o >>= 1) v = fmaxf(v, __shfl_xor_sync(0xffffffffu, v, o));
    if ((threadIdx.x & 31) == 0) sh[threadIdx.x >> 5] = v;
    __syncthreads();
    float r = sh[0];
#pragma unroll
    for (int i = 1; i < 8; i++) r = fmaxf(r, sh[i]);
    __syncthreads();
    return r;
}
__device__ __forceinline__ float blkSum(float v, float* sh) {
#pragma unroll
    for (int o = 16; o; o >>= 1) v += __shfl_xor_sync(0xffffffffu, v, o);
    if ((threadIdx.x & 31) == 0) sh[threadIdx.x >> 5] = v;
    __syncthreads();
    float r = sh[0];
#pragma unroll
    for (int i = 1; i < 8; i++) r += sh[i];
    __syncthreads();
    return r;
}

// lp: raw logits in, attn_logprob out.  lpT: log-prior^T in, log(attn_soft) out.
// soft: attn_soft out.  Pass-1 (LSE) uses fast math: its error shifts the row
// uniformly and cancels in the softmax; pass-2 keeps accurate expf/logf (MAS path).
__global__ void __launch_bounds__(256) rowsoft_kernel(
        float* __restrict__ lp, float* __restrict__ lpT,
        float* __restrict__ soft)
{
    __shared__ float sh[8];
    const size_t off = (size_t)blockIdx.x * T1_;
    const int tid = threadIdx.x;
    float v0 = lp[off + tid], v1 = lp[off + 256 + tid];
    float m  = blkMax(fmaxf(v0, v1), sh);
    float s  = blkSum(__expf(v0 - m) + __expf(v1 - m), sh);
    float lse = m + __logf(s);
    float a0 = v0 - lse + lpT[off + tid];
    float a1 = v1 - lse + lpT[off + 256 + tid];
    float m2 = blkMax(fmaxf(a0, a1), sh);
    float p0 = expf(a0 - m2), p1 = expf(a1 - m2);
    float s2 = blkSum(p0 + p1, sh);
    float inv = 1.0f / s2;
    float sm0 = p0 * inv, sm1 = p1 * inv;
    lp[off + tid] = a0;            lp[off + 256 + tid] = a1;
    soft[off + tid] = sm0;         soft[off + 256 + tid] = sm1;
    lpT[off + tid] = logf(sm0);    lpT[off + 256 + tid] = logf(sm1);
}

__global__ void zero_kernel(float4* __restrict__ p) {
    size_t i = (size_t)blockIdx.x * blockDim.x + threadIdx.x;
    p[i] = make_float4(0.f, 0.f, 0.f, 0.f);
}

#define MAS_RING 8
#define MAS_SMEM (T2_*32*2 + T1_*4)

__global__ void __launch_bounds__(32) mas_kernel(
        const float* __restrict__ la, const int* __restrict__ enc_len,
        const int* __restrict__ dec_len, float* __restrict__ hard,
        float* __restrict__ dur)
{
    extern __shared__ unsigned short sBits[];
    int* durS = (int*)&sBits[T2_*32];
    const int b = blockIdx.x;
    const int lane = threadIdx.x;
    const int el = enc_len[b];
    const int dl = dec_len[b];
    const float* rowbase = la + (size_t)b*T2_*T1_ + lane*16;

    unsigned validbits = 0u;
    float logp[16];
#pragma unroll
    for (int k = 0; k < 16; k++) {
        logp[k] = (lane == 0 && k == 0) ? 0.f : NEGV;
        if (lane*16 + k < el) validbits |= (1u << k);
    }
    float4 ring[MAS_RING][4];
#pragma unroll
    for (int p = 0; p < MAS_RING; p++)
#pragma unroll
        for (int q = 0; q < 4; q++)
            ring[p][q] = *(const float4*)(rowbase + (size_t)p*T1_ + q*4);

    for (int t2b = 0; t2b < T2_; t2b += MAS_RING) {
#pragma unroll
        for (int u = 0; u < MAS_RING; u++) {
            const int t2 = t2b + u;
            float rv[16];
            rv[0]=ring[u][0].x;  rv[1]=ring[u][0].y;  rv[2]=ring[u][0].z;  rv[3]=ring[u][0].w;
            rv[4]=ring[u][1].x;  rv[5]=ring[u][1].y;  rv[6]=ring[u][1].z;  rv[7]=ring[u][1].w;
            rv[8]=ring[u][2].x;  rv[9]=ring[u][2].y;  rv[10]=ring[u][2].z; rv[11]=ring[u][2].w;
            rv[12]=ring[u][3].x; rv[13]=ring[u][3].y; rv[14]=ring[u][3].z; rv[15]=ring[u][3].w;
            const int tn = t2 + MAS_RING;
            if (tn < T2_) {
#pragma unroll
                for (int q = 0; q < 4; q++)
                    ring[u][q] = *(const float4*)(rowbase + (size_t)tn*T1_ + q*4);
            }
#pragma unroll
            for (int k = 0; k < 16; k++)
                rv[k] = ((validbits >> k) & 1u) ? rv[k] : NEGV;
            if (t2 == 0) {
#pragma unroll
                for (int k = 0; k < 16; k++)
                    if (lane > 0 || k > 0) rv[k] = NEGV;
            }
            float last = __shfl_up_sync(0xffffffffu, logp[15], 1);
            unsigned bits = 0u;
#pragma unroll
            for (int k = 15; k >= 0; k--) {
                float sh = (k == 0) ? last : logp[k-1];
                bool t1pos = (k > 0) || (lane > 0);
                bool take = t1pos && (sh >= logp[k]);
                float base = take ? sh : logp[k];
                if (take) bits |= (1u << k);
                logp[k] = rv[k] + base;
            }
            sBits[t2*32 + lane] = (unsigned short)bits;
        }
    }
    __syncwarp();
    for (int i = lane; i < T1_; i += 32) durS[i] = 0;
    __syncwarp();
    if (lane == 0) {
        int curr = el - 1;
        for (int i = T2_-1; i >= 0; --i) {
            if (i < dl) {
                hard[((size_t)b*T2_ + i)*T1_ + curr] = 1.0f;
                durS[curr]++;
                unsigned bits = sBits[i*32 + (curr >> 4)];
                curr -= (int)((bits >> (curr & 15)) & 1u);
            }
        }
    }
    __syncwarp();
    for (int i = lane; i < T1_; i += 32) dur[(size_t)b*T1_ + i] = (float)durS[i];
}

extern "C" void kernel_launch(void* const* d_in, const int* in_sizes, int n_in,
                              void* d_out, int out_size)
{
    const float* enc_in  = (const float*)d_in[0];
    const float* dec_in  = (const float*)d_in[1];
    const int*   enc_len = (const int*)d_in[2];
    const int*   dec_len = (const int*)d_in[3];
    const float* prior   = (const float*)d_in[5];
    const float* kw1 = (const float*)d_in[6];
    const float* kb1 = (const float*)d_in[7];
    const float* kw2 = (const float*)d_in[8];
    const float* kb2 = (const float*)d_in[9];
    const float* qw1 = (const float*)d_in[10];
    const float* qb1 = (const float*)d_in[11];
    const float* qw2 = (const float*)d_in[12];
    const float* qb2 = (const float*)d_in[13];
    const float* qw3 = (const float*)d_in[14];
    const float* qb3 = (const float*)d_in[15];

    float* outp = (float*)d_out;
    const size_t VOL = (size_t)B_*T2_*T1_;
    float* lp   = outp;
    float* soft = outp + VOL;
    float* hard = outp + 2*VOL;
    float* dur  = outp + 3*VOL;

    float *pK1, *pK, *pQA, *pQB, *pk2, *pq2, *plpT;
    cudaGetSymbolAddress((void**)&pK1,  g_K1);
    cudaGetSymbolAddress((void**)&pK,   g_K);
    cudaGetSymbolAddress((void**)&pQA,  g_QA);
    cudaGetSymbolAddress((void**)&pQB,  g_QB);
    cudaGetSymbolAddress((void**)&pk2,  g_k2);
    cudaGetSymbolAddress((void**)&pq2,  g_q2);
    cudaGetSymbolAddress((void**)&plpT, g_lpT);

    transpose_logprior<<<dim3(T1_/32, T2_/32, B_), dim3(32, 8)>>>(prior, plpT);

    conv_lrelu<CENC, 3, 1, T1_><<<dim3(T1_/64, B_), 128>>>(enc_in, kw1, kb1, pK1);
    conv_lrelu<HCH,  3, 1, T1_><<<dim3(T1_/64, B_), 128>>>(pK1,    kw2, kb2, pK);
    conv_lrelu<HCH,  7, 3, T2_><<<dim3(T2_/64, B_), 128>>>(dec_in, qw1, qb1, pQA);
    conv_lrelu<HCH,  7, 3, T2_><<<dim3(T2_/64, B_), 128>>>(pQA,    qw2, qb2, pQB);
    conv_lrelu<HCH,  7, 3, T2_><<<dim3(T2_/64, B_), 128>>>(pQB,    qw3, qb3, pQA);

    sumsq_kernel<HCH, T1_><<<B_*T1_/256, 256>>>(pK,  pk2);
    sumsq_kernel<HCH, T2_><<<B_*T2_/256, 256>>>(pQA, pq2);

    attn_raw_kernel<<<dim3(T2_/32, B_), 256>>>(pQA, pK, pq2, pk2, lp);
    rowsoft_kernel<<<B_*T2_, 256>>>(lp, plpT, soft);

    zero_kernel<<<(unsigned)(VOL/4/256), 256>>>((float4*)hard);

    static int smem_set = 0;
    if (!smem_set) {
        cudaFuncSetAttribute(mas_kernel, cudaFuncAttributeMaxDynamicSharedMemorySize, MAS_SMEM);
        smem_set = 1;
    }
    mas_kernel<<<B_, 32, MAS_SMEM>>>(plpT, enc_len, dec_len, hard, dur);
}

// round 9
// speedup vs baseline: 1.0686x; 1.0636x over previous
#include <cuda_runtime.h>
#include <cuda_bf16.h>
#include <cstdint>
#include <cstddef>

#define B_    32
#define T1_   512
#define T2_   2048
#define CENC  512
#define HCH   80
#define SLOPE_ 0.3f
#define TEMP_  0.0005f
#define NEGV  -1000000000.0f

__device__ float g_K1[B_*HCH*T1_];
__device__ float g_K [B_*HCH*T1_];
__device__ float g_QA[B_*HCH*T2_];
__device__ float g_QB[B_*HCH*T2_];
__device__ float g_k2[B_*T1_];
__device__ float g_q2[B_*T2_];
__device__ float g_lpT[(size_t)B_*T2_*T1_];   // log-prior^T, then reused for log(attn_soft)

// ---------------- mma.sync helpers (base sm_80+ ISA, works on compute_103) ---
__device__ __forceinline__ uint32_t smem_u32(const void* p) {
    uint32_t a;
    asm("{ .reg .u64 t; cvta.to.shared.u64 t, %1; cvt.u32.u64 %0, t; }" : "=r"(a) : "l"(p));
    return a;
}
__device__ __forceinline__ void ldmat4(uint32_t* r, uint32_t addr) {
    asm volatile("ldmatrix.sync.aligned.m8n8.x4.shared.b16 {%0,%1,%2,%3}, [%4];"
        : "=r"(r[0]), "=r"(r[1]), "=r"(r[2]), "=r"(r[3]) : "r"(addr));
}
__device__ __forceinline__ void ldmat2(uint32_t* r, uint32_t addr) {
    asm volatile("ldmatrix.sync.aligned.m8n8.x2.shared.b16 {%0,%1}, [%2];"
        : "=r"(r[0]), "=r"(r[1]) : "r"(addr));
}
__device__ __forceinline__ void mma16816(float* d, const uint32_t* a, const uint32_t* b) {
    asm volatile("mma.sync.aligned.m16n8k16.row.col.f32.bf16.bf16.f32 "
        "{%0,%1,%2,%3}, {%4,%5,%6,%7}, {%8,%9}, {%0,%1,%2,%3};"
        : "+f"(d[0]), "+f"(d[1]), "+f"(d[2]), "+f"(d[3])
        : "r"(a[0]), "r"(a[1]), "r"(a[2]), "r"(a[3]), "r"(b[0]), "r"(b[1]));
}

// smem layout (bf16 tiles stride 88 elems = 176 B)
#define AT_STRIDE 88
#define AT_TILE   (128*AT_STRIDE*2)       // 22528 B
#define SM_AH 0
#define SM_AL (SM_AH + AT_TILE)
#define SM_BH (SM_AL + AT_TILE)
#define SM_BL (SM_BH + AT_TILE)
#define SM_Q2 (SM_BL + AT_TILE)
#define SM_K2 (SM_Q2 + 512)
#define ATTN_SMEM (SM_K2 + 512)
#define SM_OUT 0                           // reuse A/B region; 128*132*4 = 67584 B
#define OUT_STRIDE 132

// out[b, t2, t1] = TEMP*(2*sum_c Q[b,c,t2] K[b,c,t1] - q2 - k2)
// 256 threads = 8 warps, warp grid 2(m) x 4(n), each warp 64x32 of the 128x128 tile
__global__ void __launch_bounds__(256) attn_mma_kernel(
        const float* __restrict__ Q, const float* __restrict__ K,
        const float* __restrict__ q2s, const float* __restrict__ k2s,
        float* __restrict__ outp)
{
    extern __shared__ char smem[];
    const uint32_t smb = smem_u32(smem);
    const int tid  = threadIdx.x;
    const int wid  = tid >> 5;
    const int lane = tid & 31;
    const int t2_0 = blockIdx.x * 128;
    const int t1_0 = blockIdx.y * 128;
    const int b    = blockIdx.z;

    // fill A (Q side, rows=t2) and B (K side, rows=t1), bf16 hi/lo, K-contiguous
    for (int idx = tid; idx < HCH*128; idx += 256) {
        int c = idx >> 7, row = idx & 127;
        float v = Q[((size_t)b*HCH + c)*T2_ + t2_0 + row];
        __nv_bfloat16 h = __float2bfloat16(v);
        __nv_bfloat16 l = __float2bfloat16(v - __bfloat162float(h));
        *(__nv_bfloat16*)(smem + SM_AH + (row*AT_STRIDE + c)*2) = h;
        *(__nv_bfloat16*)(smem + SM_AL + (row*AT_STRIDE + c)*2) = l;
    }
    for (int idx = tid; idx < HCH*128; idx += 256) {
        int c = idx >> 7, row = idx & 127;
        float v = K[((size_t)b*HCH + c)*T1_ + t1_0 + row];
        __nv_bfloat16 h = __float2bfloat16(v);
        __nv_bfloat16 l = __float2bfloat16(v - __bfloat162float(h));
        *(__nv_bfloat16*)(smem + SM_BH + (row*AT_STRIDE + c)*2) = h;
        *(__nv_bfloat16*)(smem + SM_BL + (row*AT_STRIDE + c)*2) = l;
    }
    if (tid < 128) {
        *(float*)(smem + SM_Q2 + tid*4) = q2s[(size_t)b*T2_ + t2_0 + tid];
        *(float*)(smem + SM_K2 + tid*4) = k2s[(size_t)b*T1_ + t1_0 + tid];
    }
    __syncthreads();

    const int m_blk = (wid & 1) * 64;     // t2 offset of this warp's 64x32 tile
    const int n_blk = (wid >> 1) * 32;    // t1 offset (8 warps -> 0,32,64,96)

    float acc[4][4][4];
#pragma unroll
    for (int mi = 0; mi < 4; mi++)
#pragma unroll
        for (int ni = 0; ni < 4; ni++)
#pragma unroll
            for (int q = 0; q < 4; q++) acc[mi][ni][q] = 0.f;

    const uint32_t a_lrow = (uint32_t)(lane & 15);
    const uint32_t a_lcol = (uint32_t)((lane >> 4) << 3);
    const uint32_t b_lrow = (uint32_t)(lane & 7);
    const uint32_t b_lcol = (uint32_t)(((lane >> 3) & 1) << 3);

#pragma unroll
    for (int ks = 0; ks < 5; ks++) {
        const uint32_t kc = ks * 16;
        uint32_t Ah[4][4], Al[4][4], Bh[4][2], Bl[4][2];
#pragma unroll
        for (int mi = 0; mi < 4; mi++) {
            uint32_t off = ((m_blk + mi*16 + a_lrow)*AT_STRIDE + kc + a_lcol)*2;
            ldmat4(Ah[mi], smb + SM_AH + off);
            ldmat4(Al[mi], smb + SM_AL + off);
        }
#pragma unroll
        for (int ni = 0; ni < 4; ni++) {
            uint32_t off = ((n_blk + ni*8 + b_lrow)*AT_STRIDE + kc + b_lcol)*2;
            ldmat2(Bh[ni], smb + SM_BH + off);
            ldmat2(Bl[ni], smb + SM_BL + off);
        }
#pragma unroll
        for (int mi = 0; mi < 4; mi++)
#pragma unroll
            for (int ni = 0; ni < 4; ni++) {
                mma16816(acc[mi][ni], Ah[mi], Bh[ni]);
                mma16816(acc[mi][ni], Ah[mi], Bl[ni]);
                mma16816(acc[mi][ni], Al[mi], Bh[ni]);
            }
    }
    __syncthreads();   // done reading A/B smem; SM_OUT aliases it

    // epilogue: apply TEMP*(2qk - q2 - k2), write to smem bounce tile
    const int gid = lane >> 2, tig = lane & 3;
    const float* sQ2 = (const float*)(smem + SM_Q2);
    const float* sK2 = (const float*)(smem + SM_K2);
#pragma unroll
    for (int mi = 0; mi < 4; mi++) {
        int r0 = m_blk + mi*16 + gid;
        int r1 = r0 + 8;
        float q20 = sQ2[r0], q21 = sQ2[r1];
#pragma unroll
        for (int ni = 0; ni < 4; ni++) {
            int c0 = n_blk + ni*8 + tig*2;
            float k20 = sK2[c0], k21 = sK2[c0 + 1];
            float2 lo, hi;
            lo.x = TEMP_*(2.f*acc[mi][ni][0] - q20 - k20);
            lo.y = TEMP_*(2.f*acc[mi][ni][1] - q20 - k21);
            hi.x = TEMP_*(2.f*acc[mi][ni][2] - q21 - k20);
            hi.y = TEMP_*(2.f*acc[mi][ni][3] - q21 - k21);
            *(float2*)(smem + SM_OUT + (r0*OUT_STRIDE + c0)*4) = lo;
            *(float2*)(smem + SM_OUT + (r1*OUT_STRIDE + c0)*4) = hi;
        }
    }
    __syncthreads();

#pragma unroll 4
    for (int it = 0; it < 16; it++) {
        int row = it*8 + (tid >> 5);
        float4 v = *(const float4*)(smem + SM_OUT + (row*OUT_STRIDE + lane*4)*4);
        *(float4*)&outp[((size_t)b*T2_ + t2_0 + row)*T1_ + t1_0 + lane*4] = v;
    }
}

// ---------------------------------------------------------------------------
__global__ void __launch_bounds__(256) transpose_logprior(
        const float* __restrict__ prior, float* __restrict__ lpT)
{
    __shared__ float tile[32][33];
    const int b = blockIdx.z;
    const int t1_0 = blockIdx.x * 32, t2_0 = blockIdx.y * 32;
    const int tx = threadIdx.x, ty = threadIdx.y;
#pragma unroll
    for (int i = 0; i < 4; i++)
        tile[ty + 8*i][tx] = prior[((size_t)b*T1_ + t1_0 + ty + 8*i)*T2_ + t2_0 + tx];
    __syncthreads();
#pragma unroll
    for (int i = 0; i < 4; i++)
        lpT[((size_t)b*T2_ + t2_0 + ty + 8*i)*T1_ + t1_0 + tx] =
            logf(tile[tx][ty + 8*i] + 1e-8f);
}

template<int CIN, int KSZ, int PAD, int TLEN>
__global__ void __launch_bounds__(128) conv_lrelu(
        const float* __restrict__ x, const float* __restrict__ wgt,
        const float* __restrict__ bias, float* __restrict__ y)
{
    constexpr int TT  = 64;
    constexpr int CB  = 16;
    constexpr int INW = TT + 8;
    constexpr int WSLOT = (KSZ <= 4) ? 4 : 8;
    constexpr int OFF = 4 - PAD;
    __shared__ float sIn[CB][INW];
    __shared__ float sW[CB*HCH*WSLOT];

    const int b   = blockIdx.y;
    const int t0  = blockIdx.x * TT;
    const int tid = threadIdx.x;
    const int tg  = tid & 7;
    const int og  = tid >> 3;

    float acc[5][8];
#pragma unroll
    for (int i = 0; i < 5; i++)
#pragma unroll
        for (int j = 0; j < 8; j++) acc[i][j] = 0.f;

    for (int c0 = 0; c0 < CIN; c0 += CB) {
        for (int idx = tid; idx < CB*INW; idx += 128) {
            int ci = idx / INW, u = idx - ci*INW;
            int t = t0 + u - 4;
            sIn[ci][u] = ((unsigned)t < (unsigned)TLEN)
                       ? x[((size_t)b*CIN + c0 + ci)*TLEN + t] : 0.f;
        }
        for (int idx = tid; idx < CB*HCH*KSZ; idx += 128) {
            int ci  = idx / (HCH*KSZ);
            int rem = idx - ci*(HCH*KSZ);
            int oc  = rem / KSZ;
            int k   = rem - oc*KSZ;
            sW[(ci*HCH + oc)*WSLOT + k] =
                wgt[(size_t)oc*CIN*KSZ + (size_t)(c0 + ci)*KSZ + k];
        }
        __syncthreads();
#pragma unroll 1
        for (int ci = 0; ci < CB; ci++) {
            float wreg[16];
            float4 a0 = *(const float4*)&sIn[ci][tg*8 + 0];
            float4 a1 = *(const float4*)&sIn[ci][tg*8 + 4];
            float4 a2 = *(const float4*)&sIn[ci][tg*8 + 8];
            float4 a3 = *(const float4*)&sIn[ci][tg*8 + 12];
            wreg[0]=a0.x; wreg[1]=a0.y; wreg[2]=a0.z; wreg[3]=a0.w;
            wreg[4]=a1.x; wreg[5]=a1.y; wreg[6]=a1.z; wreg[7]=a1.w;
            wreg[8]=a2.x; wreg[9]=a2.y; wreg[10]=a2.z; wreg[11]=a2.w;
            wreg[12]=a3.x; wreg[13]=a3.y; wreg[14]=a3.z; wreg[15]=a3.w;
#pragma unroll
            for (int i = 0; i < 5; i++) {
                const float* wp = &sW[(ci*HCH + og*5 + i)*WSLOT];
                float wf[WSLOT];
                float4 b0 = *(const float4*)wp;
                wf[0]=b0.x; wf[1]=b0.y; wf[2]=b0.z; wf[3]=b0.w;
                if (WSLOT == 8) {
                    float4 b1 = *(const float4*)(wp + 4);
                    wf[4]=b1.x; wf[5]=b1.y; wf[6]=b1.z; wf[7]=b1.w;
                }
#pragma unroll
                for (int kk = 0; kk < KSZ; kk++)
#pragma unroll
                    for (int j = 0; j < 8; j++)
                        acc[i][j] = fmaf(wf[kk], wreg[j + kk + OFF], acc[i][j]);
            }
        }
        __syncthreads();
    }
#pragma unroll
    for (int i = 0; i < 5; i++) {
        int oc = og*5 + i;
        float bv = bias[oc];
        float4 o0, o1;
        float v;
        v = acc[i][0] + bv; o0.x = v >= 0.f ? v : SLOPE_*v;
        v = acc[i][1] + bv; o0.y = v >= 0.f ? v : SLOPE_*v;
        v = acc[i][2] + bv; o0.z = v >= 0.f ? v : SLOPE_*v;
        v = acc[i][3] + bv; o0.w = v >= 0.f ? v : SLOPE_*v;
        v = acc[i][4] + bv; o1.x = v >= 0.f ? v : SLOPE_*v;
        v = acc[i][5] + bv; o1.y = v >= 0.f ? v : SLOPE_*v;
        v = acc[i][6] + bv; o1.z = v >= 0.f ? v : SLOPE_*v;
        v = acc[i][7] + bv; o1.w = v >= 0.f ? v : SLOPE_*v;
        float* yp = &y[((size_t)b*HCH + oc)*TLEN + t0 + tg*8];
        *(float4*)yp       = o0;
        *(float4*)(yp + 4) = o1;
    }
}

template<int C, int T>
__global__ void __launch_bounds__(256) sumsq_kernel(
        const float* __restrict__ x, float* __restrict__ out)
{
    int idx = blockIdx.x * 256 + threadIdx.x;
    int b = idx / T, t = idx - b*T;
    float s = 0.f;
#pragma unroll 8
    for (int c = 0; c < C; c++) {
        float v = x[((size_t)b*C + c)*T + t];
        s = fmaf(v, v, s);
    }
    out[idx] = s;
}

__device__ __forceinline__ float blkMax(float v, float* sh) {
#pragma unroll
    for (int o = 16; o; o >>= 1) v = fmaxf(v, __shfl_xor_sync(0xffffffffu, v, o));
    if ((threadIdx.x & 31) == 0) sh[threadIdx.x >> 5] = v;
    __syncthreads();
    float r = sh[0];
#pragma unroll
    for (int i = 1; i < 8; i++) r = fmaxf(r, sh[i]);
    __syncthreads();
    return r;
}
__device__ __forceinline__ float blkSum(float v, float* sh) {
#pragma unroll
    for (int o = 16; o; o >>= 1) v += __shfl_xor_sync(0xffffffffu, v, o);
    if ((threadIdx.x & 31) == 0) sh[threadIdx.x >> 5] = v;
    __syncthreads();
    float r = sh[0];
#pragma unroll
    for (int i = 1; i < 8; i++) r += sh[i];
    __syncthreads();
    return r;
}

__global__ void __launch_bounds__(256) rowsoft_kernel(
        float* __restrict__ lp, float* __restrict__ lpT,
        float* __restrict__ soft)
{
    __shared__ float sh[8];
    const size_t off = (size_t)blockIdx.x * T1_;
    const int tid = threadIdx.x;
    float v0 = lp[off + tid], v1 = lp[off + 256 + tid];
    float m  = blkMax(fmaxf(v0, v1), sh);
    float s  = blkSum(__expf(v0 - m) + __expf(v1 - m), sh);
    float lse = m + __logf(s);
    float a0 = v0 - lse + lpT[off + tid];
    float a1 = v1 - lse + lpT[off + 256 + tid];
    float m2 = blkMax(fmaxf(a0, a1), sh);
    float p0 = expf(a0 - m2), p1 = expf(a1 - m2);
    float s2 = blkSum(p0 + p1, sh);
    float inv = 1.0f / s2;
    float sm0 = p0 * inv, sm1 = p1 * inv;
    lp[off + tid] = a0;            lp[off + 256 + tid] = a1;
    soft[off + tid] = sm0;         soft[off + 256 + tid] = sm1;
    lpT[off + tid] = logf(sm0);    lpT[off + 256 + tid] = logf(sm1);
}

__global__ void zero_kernel(float4* __restrict__ p) {
    size_t i = (size_t)blockIdx.x * blockDim.x + threadIdx.x;
    p[i] = make_float4(0.f, 0.f, 0.f, 0.f);
}

#define MAS_RING 8
#define MAS_SMEM (T2_*32*2 + T1_*4)

__global__ void __launch_bounds__(32) mas_kernel(
        const float* __restrict__ la, const int* __restrict__ enc_len,
        const int* __restrict__ dec_len, float* __restrict__ hard,
        float* __restrict__ dur)
{
    extern __shared__ unsigned short sBits[];
    int* durS = (int*)&sBits[T2_*32];
    const int b = blockIdx.x;
    const int lane = threadIdx.x;
    const int el = enc_len[b];
    const int dl = dec_len[b];
    const float* rowbase = la + (size_t)b*T2_*T1_ + lane*16;

    unsigned validbits = 0u;
    float logp[16];
#pragma unroll
    for (int k = 0; k < 16; k++) {
        logp[k] = (lane == 0 && k == 0) ? 0.f : NEGV;
        if (lane*16 + k < el) validbits |= (1u << k);
    }
    float4 ring[MAS_RING][4];
#pragma unroll
    for (int p = 0; p < MAS_RING; p++)
#pragma unroll
        for (int q = 0; q < 4; q++)
            ring[p][q] = *(const float4*)(rowbase + (size_t)p*T1_ + q*4);

    for (int t2b = 0; t2b < T2_; t2b += MAS_RING) {
#pragma unroll
        for (int u = 0; u < MAS_RING; u++) {
            const int t2 = t2b + u;
            float rv[16];
            rv[0]=ring[u][0].x;  rv[1]=ring[u][0].y;  rv[2]=ring[u][0].z;  rv[3]=ring[u][0].w;
            rv[4]=ring[u][1].x;  rv[5]=ring[u][1].y;  rv[6]=ring[u][1].z;  rv[7]=ring[u][1].w;
            rv[8]=ring[u][2].x;  rv[9]=ring[u][2].y;  rv[10]=ring[u][2].z; rv[11]=ring[u][2].w;
            rv[12]=ring[u][3].x; rv[13]=ring[u][3].y; rv[14]=ring[u][3].z; rv[15]=ring[u][3].w;
            const int tn = t2 + MAS_RING;
            if (tn < T2_) {
#pragma unroll
                for (int q = 0; q < 4; q++)
                    ring[u][q] = *(const float4*)(rowbase + (size_t)tn*T1_ + q*4);
            }
#pragma unroll
            for (int k = 0; k < 16; k++)
                rv[k] = ((validbits >> k) & 1u) ? rv[k] : NEGV;
            if (t2 == 0) {
#pragma unroll
                for (int k = 0; k < 16; k++)
                    if (lane > 0 || k > 0) rv[k] = NEGV;
            }
            float last = __shfl_up_sync(0xffffffffu, logp[15], 1);
            unsigned bits = 0u;
#pragma unroll
            for (int k = 15; k >= 0; k--) {
                float sh = (k == 0) ? last : logp[k-1];
                bool t1pos = (k > 0) || (lane > 0);
                bool take = t1pos && (sh >= logp[k]);
                float base = take ? sh : logp[k];
                if (take) bits |= (1u << k);
                logp[k] = rv[k] + base;
            }
            sBits[t2*32 + lane] = (unsigned short)bits;
        }
    }
    __syncwarp();
    for (int i = lane; i < T1_; i += 32) durS[i] = 0;
    __syncwarp();
    if (lane == 0) {
        int curr = el - 1;
        for (int i = T2_-1; i >= 0; --i) {
            if (i < dl) {
                hard[((size_t)b*T2_ + i)*T1_ + curr] = 1.0f;
                durS[curr]++;
                unsigned bits = sBits[i*32 + (curr >> 4)];
                curr -= (int)((bits >> (curr & 15)) & 1u);
            }
        }
    }
    __syncwarp();
    for (int i = lane; i < T1_; i += 32) dur[(size_t)b*T1_ + i] = (float)durS[i];
}

extern "C" void kernel_launch(void* const* d_in, const int* in_sizes, int n_in,
                              void* d_out, int out_size)
{
    const float* enc_in  = (const float*)d_in[0];
    const float* dec_in  = (const float*)d_in[1];
    const int*   enc_len = (const int*)d_in[2];
    const int*   dec_len = (const int*)d_in[3];
    const float* prior   = (const float*)d_in[5];
    const float* kw1 = (const float*)d_in[6];
    const float* kb1 = (const float*)d_in[7];
    const float* kw2 = (const float*)d_in[8];
    const float* kb2 = (const float*)d_in[9];
    const float* qw1 = (const float*)d_in[10];
    const float* qb1 = (const float*)d_in[11];
    const float* qw2 = (const float*)d_in[12];
    const float* qb2 = (const float*)d_in[13];
    const float* qw3 = (const float*)d_in[14];
    const float* qb3 = (const float*)d_in[15];

    float* outp = (float*)d_out;
    const size_t VOL = (size_t)B_*T2_*T1_;
    float* lp   = outp;
    float* soft = outp + VOL;
    float* hard = outp + 2*VOL;
    float* dur  = outp + 3*VOL;

    float *pK1, *pK, *pQA, *pQB, *pk2, *pq2, *plpT;
    cudaGetSymbolAddress((void**)&pK1,  g_K1);
    cudaGetSymbolAddress((void**)&pK,   g_K);
    cudaGetSymbolAddress((void**)&pQA,  g_QA);
    cudaGetSymbolAddress((void**)&pQB,  g_QB);
    cudaGetSymbolAddress((void**)&pk2,  g_k2);
    cudaGetSymbolAddress((void**)&pq2,  g_q2);
    cudaGetSymbolAddress((void**)&plpT, g_lpT);

    static int attrs_set = 0;
    if (!attrs_set) {
        cudaFuncSetAttribute(mas_kernel, cudaFuncAttributeMaxDynamicSharedMemorySize, MAS_SMEM);
        cudaFuncSetAttribute(attn_mma_kernel, cudaFuncAttributeMaxDynamicSharedMemorySize, ATTN_SMEM);
        attrs_set = 1;
    }

    transpose_logprior<<<dim3(T1_/32, T2_/32, B_), dim3(32, 8)>>>(prior, plpT);

    conv_lrelu<CENC, 3, 1, T1_><<<dim3(T1_/64, B_), 128>>>(enc_in, kw1, kb1, pK1);
    conv_lrelu<HCH,  3, 1, T1_><<<dim3(T1_/64, B_), 128>>>(pK1,    kw2, kb2, pK);
    conv_lrelu<HCH,  7, 3, T2_><<<dim3(T2_/64, B_), 128>>>(dec_in, qw1, qb1, pQA);
    conv_lrelu<HCH,  7, 3, T2_><<<dim3(T2_/64, B_), 128>>>(pQA,    qw2, qb2, pQB);
    conv_lrelu<HCH,  7, 3, T2_><<<dim3(T2_/64, B_), 128>>>(pQB,    qw3, qb3, pQA);

    sumsq_kernel<HCH, T1_><<<B_*T1_/256, 256>>>(pK,  pk2);
    sumsq_kernel<HCH, T2_><<<B_*T2_/256, 256>>>(pQA, pq2);

    attn_mma_kernel<<<dim3(T2_/128, T1_/128, B_), 256, ATTN_SMEM>>>(pQA, pK, pq2, pk2, lp);
    rowsoft_kernel<<<B_*T2_, 256>>>(lp, plpT, soft);

    zero_kernel<<<(unsigned)(VOL/4/256), 256>>>((float4*)hard);

    mas_kernel<<<B_, 32, MAS_SMEM>>>(plpT, enc_len, dec_len, hard, dur);
}

// round 11
// speedup vs baseline: 1.2918x; 1.2089x over previous
#include <cuda_runtime.h>
#include <cuda_bf16.h>
#include <cstdint>
#include <cstddef>

#define B_    32
#define T1_   512
#define T2_   2048
#define CENC  512
#define HCH   80
#define SLOPE_ 0.3f
#define TEMP_  0.0005f
#define NEGV  -1000000000.0f

__device__ float g_K1[B_*HCH*T1_];
__device__ float g_K [B_*HCH*T1_];
__device__ float g_QA[B_*HCH*T2_];
__device__ float g_QB[B_*HCH*T2_];
__device__ float g_k2[B_*T1_];
__device__ float g_q2[B_*T2_];
__device__ float g_lpT[(size_t)B_*T2_*T1_];   // log-prior^T, then reused for log(attn_soft)

// ---------------- mma.sync helpers (base sm_80+ ISA) -------------------------
__device__ __forceinline__ uint32_t smem_u32(const void* p) {
    uint32_t a;
    asm("{ .reg .u64 t; cvta.to.shared.u64 t, %1; cvt.u32.u64 %0, t; }" : "=r"(a) : "l"(p));
    return a;
}
__device__ __forceinline__ void ldmat4(uint32_t* r, uint32_t addr) {
    asm volatile("ldmatrix.sync.aligned.m8n8.x4.shared.b16 {%0,%1,%2,%3}, [%4];"
        : "=r"(r[0]), "=r"(r[1]), "=r"(r[2]), "=r"(r[3]) : "r"(addr));
}
__device__ __forceinline__ void ldmat2(uint32_t* r, uint32_t addr) {
    asm volatile("ldmatrix.sync.aligned.m8n8.x2.shared.b16 {%0,%1}, [%2];"
        : "=r"(r[0]), "=r"(r[1]) : "r"(addr));
}
__device__ __forceinline__ void mma16816(float* d, const uint32_t* a, const uint32_t* b) {
    asm volatile("mma.sync.aligned.m16n8k16.row.col.f32.bf16.bf16.f32 "
        "{%0,%1,%2,%3}, {%4,%5,%6,%7}, {%8,%9}, {%0,%1,%2,%3};"
        : "+f"(d[0]), "+f"(d[1]), "+f"(d[2]), "+f"(d[3])
        : "r"(a[0]), "r"(a[1]), "r"(a[2]), "r"(a[3]), "r"(b[0]), "r"(b[1]));
}
__device__ __forceinline__ void bf16split(float v, __nv_bfloat16& h, __nv_bfloat16& l) {
    h = __float2bfloat16(v);
    l = __float2bfloat16(v - __bfloat162float(h));
}

// =================== attn distance GEMM (validated round 9) =================
#define AT_STRIDE 88
#define AT_TILE   (128*AT_STRIDE*2)
#define SM_AH 0
#define SM_AL (SM_AH + AT_TILE)
#define SM_BH (SM_AL + AT_TILE)
#define SM_BL (SM_BH + AT_TILE)
#define SM_Q2 (SM_BL + AT_TILE)
#define SM_K2 (SM_Q2 + 512)
#define ATTN_SMEM (SM_K2 + 512)
#define SM_OUT 0
#define OUT_STRIDE 132

__global__ void __launch_bounds__(256) attn_mma_kernel(
        const float* __restrict__ Q, const float* __restrict__ K,
        const float* __restrict__ q2s, const float* __restrict__ k2s,
        float* __restrict__ outp)
{
    extern __shared__ char smem[];
    const uint32_t smb = smem_u32(smem);
    const int tid  = threadIdx.x;
    const int wid  = tid >> 5;
    const int lane = tid & 31;
    const int t2_0 = blockIdx.x * 128;
    const int t1_0 = blockIdx.y * 128;
    const int b    = blockIdx.z;

    for (int idx = tid; idx < HCH*128; idx += 256) {
        int c = idx >> 7, row = idx & 127;
        __nv_bfloat16 h, l;
        bf16split(Q[((size_t)b*HCH + c)*T2_ + t2_0 + row], h, l);
        *(__nv_bfloat16*)(smem + SM_AH + (row*AT_STRIDE + c)*2) = h;
        *(__nv_bfloat16*)(smem + SM_AL + (row*AT_STRIDE + c)*2) = l;
    }
    for (int idx = tid; idx < HCH*128; idx += 256) {
        int c = idx >> 7, row = idx & 127;
        __nv_bfloat16 h, l;
        bf16split(K[((size_t)b*HCH + c)*T1_ + t1_0 + row], h, l);
        *(__nv_bfloat16*)(smem + SM_BH + (row*AT_STRIDE + c)*2) = h;
        *(__nv_bfloat16*)(smem + SM_BL + (row*AT_STRIDE + c)*2) = l;
    }
    if (tid < 128) {
        *(float*)(smem + SM_Q2 + tid*4) = q2s[(size_t)b*T2_ + t2_0 + tid];
        *(float*)(smem + SM_K2 + tid*4) = k2s[(size_t)b*T1_ + t1_0 + tid];
    }
    __syncthreads();

    const int m_blk = (wid & 1) * 64;
    const int n_blk = (wid >> 1) * 32;

    float acc[4][4][4];
#pragma unroll
    for (int mi = 0; mi < 4; mi++)
#pragma unroll
        for (int ni = 0; ni < 4; ni++)
#pragma unroll
            for (int q = 0; q < 4; q++) acc[mi][ni][q] = 0.f;

    const uint32_t a_lrow = (uint32_t)(lane & 15);
    const uint32_t a_lcol = (uint32_t)((lane >> 4) << 3);
    const uint32_t b_lrow = (uint32_t)(lane & 7);
    const uint32_t b_lcol = (uint32_t)(((lane >> 3) & 1) << 3);

#pragma unroll
    for (int ks = 0; ks < 5; ks++) {
        const uint32_t kc = ks * 16;
        uint32_t Ah[4][4], Al[4][4], Bh[4][2], Bl[4][2];
#pragma unroll
        for (int mi = 0; mi < 4; mi++) {
            uint32_t off = ((m_blk + mi*16 + a_lrow)*AT_STRIDE + kc + a_lcol)*2;
            ldmat4(Ah[mi], smb + SM_AH + off);
            ldmat4(Al[mi], smb + SM_AL + off);
        }
#pragma unroll
        for (int ni = 0; ni < 4; ni++) {
            uint32_t off = ((n_blk + ni*8 + b_lrow)*AT_STRIDE + kc + b_lcol)*2;
            ldmat2(Bh[ni], smb + SM_BH + off);
            ldmat2(Bl[ni], smb + SM_BL + off);
        }
#pragma unroll
        for (int mi = 0; mi < 4; mi++)
#pragma unroll
            for (int ni = 0; ni < 4; ni++) {
                mma16816(acc[mi][ni], Ah[mi], Bh[ni]);
                mma16816(acc[mi][ni], Ah[mi], Bl[ni]);
                mma16816(acc[mi][ni], Al[mi], Bh[ni]);
            }
    }
    __syncthreads();

    const int gid = lane >> 2, tig = lane & 3;
    const float* sQ2 = (const float*)(smem + SM_Q2);
    const float* sK2 = (const float*)(smem + SM_K2);
#pragma unroll
    for (int mi = 0; mi < 4; mi++) {
        int r0 = m_blk + mi*16 + gid;
        int r1 = r0 + 8;
        float q20 = sQ2[r0], q21 = sQ2[r1];
#pragma unroll
        for (int ni = 0; ni < 4; ni++) {
            int c0 = n_blk + ni*8 + tig*2;
            float k20 = sK2[c0], k21 = sK2[c0 + 1];
            float2 lo, hi;
            lo.x = TEMP_*(2.f*acc[mi][ni][0] - q20 - k20);
            lo.y = TEMP_*(2.f*acc[mi][ni][1] - q20 - k21);
            hi.x = TEMP_*(2.f*acc[mi][ni][2] - q21 - k20);
            hi.y = TEMP_*(2.f*acc[mi][ni][3] - q21 - k21);
            *(float2*)(smem + SM_OUT + (r0*OUT_STRIDE + c0)*4) = lo;
            *(float2*)(smem + SM_OUT + (r1*OUT_STRIDE + c0)*4) = hi;
        }
    }
    __syncthreads();
#pragma unroll 4
    for (int it = 0; it < 16; it++) {
        int row = it*8 + (tid >> 5);
        float4 v = *(const float4*)(smem + SM_OUT + (row*OUT_STRIDE + lane*4)*4);
        *(float4*)&outp[((size_t)b*T2_ + t2_0 + row)*T1_ + t1_0 + lane*4] = v;
    }
}

// =================== conv (CIN=80) as tap-shifted GEMM on mma.sync ==========
// Y[t, oc] = sum_k sum_c X[t+k-PAD, c] * Wk[oc, c];  128 t-rows per CTA.
// smem: X tile [TT+KSZ-1][88] bf16 hi/lo; W one tap [80][88] hi/lo; bias; 
// transpose bounce tile reuses X region.
#define CV_STRIDE 88
#define CV_XROWS  136                         // >= 128 + KSZ-1
#define CV_XHALF  (CV_XROWS*CV_STRIDE*2)      // 23936
#define CV_XH 0
#define CV_XL CV_XHALF
#define CV_WH (2*CV_XHALF)                    // 47872
#define CV_WHALF (HCH*CV_STRIDE*2)            // 14080
#define CV_WL (CV_WH + CV_WHALF)
#define CV_BIAS (CV_WH + 2*CV_WHALF)          // 76032
#define CONV_SMEM (CV_BIAS + 512)
#define CV_TOUT 0                              // [oc][132] floats reuses X region
#define CV_TSTR 132

template<int KSZ, int PAD, int TLEN>
__global__ void __launch_bounds__(256) conv_mma_kernel(
        const float* __restrict__ x, const float* __restrict__ wgt,
        const float* __restrict__ bias, float* __restrict__ y)
{
    extern __shared__ char smem[];
    const uint32_t smb = smem_u32(smem);
    const int tid  = threadIdx.x;
    const int wid  = tid >> 5;
    const int lane = tid & 31;
    const int t0   = blockIdx.x * 128;
    const int b    = blockIdx.y;
    constexpr int XR = 128 + KSZ - 1;          // rows actually used

    // load X tile: smem row r <-> input t = t0 + r - PAD
    for (int idx = tid; idx < HCH*XR; idx += 256) {
        int c = idx / XR, r = idx - c*XR;
        int t = t0 + r - PAD;
        float v = ((unsigned)t < (unsigned)TLEN) ? x[((size_t)b*HCH + c)*TLEN + t] : 0.f;
        __nv_bfloat16 h, l;
        bf16split(v, h, l);
        *(__nv_bfloat16*)(smem + CV_XH + (r*CV_STRIDE + c)*2) = h;
        *(__nv_bfloat16*)(smem + CV_XL + (r*CV_STRIDE + c)*2) = l;
    }
    if (tid < HCH) *(float*)(smem + CV_BIAS + tid*4) = bias[tid];

    const int m_blk = (wid >> 1) * 32;         // 4 groups x 32 t-rows
    const int n_blk = (wid & 1) * 40;          // 2 groups x 40 oc (5 n8 tiles)

    float acc[2][5][4];
#pragma unroll
    for (int mi = 0; mi < 2; mi++)
#pragma unroll
        for (int ni = 0; ni < 5; ni++)
#pragma unroll
            for (int q = 0; q < 4; q++) acc[mi][ni][q] = 0.f;

    const uint32_t a_lrow = (uint32_t)(lane & 15);
    const uint32_t a_lcol = (uint32_t)((lane >> 4) << 3);
    const uint32_t b_lrow = (uint32_t)(lane & 7);
    const uint32_t b_lcol = (uint32_t)(((lane >> 3) & 1) << 3);

#pragma unroll 1
    for (int k = 0; k < KSZ; k++) {
        __syncthreads();   // protect W buffer (also covers X on first iter)
        for (int idx = tid; idx < HCH*HCH; idx += 256) {
            int oc = idx / HCH, c = idx - oc*HCH;
            __nv_bfloat16 h, l;
            bf16split(wgt[((size_t)oc*HCH + c)*KSZ + k], h, l);
            *(__nv_bfloat16*)(smem + CV_WH + (oc*CV_STRIDE + c)*2) = h;
            *(__nv_bfloat16*)(smem + CV_WL + (oc*CV_STRIDE + c)*2) = l;
        }
        __syncthreads();
#pragma unroll
        for (int ks = 0; ks < 5; ks++) {
            const uint32_t kc = ks * 16;
            uint32_t Ah[2][4], Al[2][4], Bh[5][2], Bl[5][2];
#pragma unroll
            for (int mi = 0; mi < 2; mi++) {
                uint32_t off = ((uint32_t)(m_blk + mi*16 + k + a_lrow)*CV_STRIDE + kc + a_lcol)*2;
                ldmat4(Ah[mi], smb + CV_XH + off);
                ldmat4(Al[mi], smb + CV_XL + off);
            }
#pragma unroll
            for (int ni = 0; ni < 5; ni++) {
                uint32_t off = ((uint32_t)(n_blk + ni*8 + b_lrow)*CV_STRIDE + kc + b_lcol)*2;
                ldmat2(Bh[ni], smb + CV_WH + off);
                ldmat2(Bl[ni], smb + CV_WL + off);
            }
#pragma unroll
            for (int mi = 0; mi < 2; mi++)
#pragma unroll
                for (int ni = 0; ni < 5; ni++) {
                    mma16816(acc[mi][ni], Ah[mi], Bh[ni]);
                    mma16816(acc[mi][ni], Ah[mi], Bl[ni]);
                    mma16816(acc[mi][ni], Al[mi], Bh[ni]);
                }
        }
    }
    __syncthreads();   // done with X/W smem; transpose tile reuses it

    // bias + leaky relu, write transposed [oc][t] bounce tile
    const int gid = lane >> 2, tig = lane & 3;
    const float* sB = (const float*)(smem + CV_BIAS);
#pragma unroll
    for (int mi = 0; mi < 2; mi++) {
        int r0 = m_blk + mi*16 + gid;   // t-row
        int r1 = r0 + 8;
#pragma unroll
        for (int ni = 0; ni < 5; ni++) {
            int c0 = n_blk + ni*8 + tig*2;
            float b0 = sB[c0], b1 = sB[c0+1];
            float v;
            v = acc[mi][ni][0] + b0; v = v >= 0.f ? v : SLOPE_*v;
            *(float*)(smem + CV_TOUT + (c0*CV_TSTR + r0)*4) = v;
            v = acc[mi][ni][1] + b1; v = v >= 0.f ? v : SLOPE_*v;
            *(float*)(smem + CV_TOUT + ((c0+1)*CV_TSTR + r0)*4) = v;
            v = acc[mi][ni][2] + b0; v = v >= 0.f ? v : SLOPE_*v;
            *(float*)(smem + CV_TOUT + (c0*CV_TSTR + r1)*4) = v;
            v = acc[mi][ni][3] + b1; v = v >= 0.f ? v : SLOPE_*v;
            *(float*)(smem + CV_TOUT + ((c0+1)*CV_TSTR + r1)*4) = v;
        }
    }
    __syncthreads();
    // coalesced store: 80 oc x 32 float4
    for (int idx = tid; idx < HCH*32; idx += 256) {
        int oc = idx >> 5, t4 = idx & 31;
        float4 v = *(const float4*)(smem + CV_TOUT + (oc*CV_TSTR + t4*4)*4);
        *(float4*)&y[((size_t)b*HCH + oc)*TLEN + t0 + t4*4] = v;
    }
}

// ---------------------------------------------------------------------------
__global__ void __launch_bounds__(256) transpose_logprior(
        const float* __restrict__ prior, float* __restrict__ lpT)
{
    __shared__ float tile[32][33];
    const int b = blockIdx.z;
    const int t1_0 = blockIdx.x * 32, t2_0 = blockIdx.y * 32;
    const int tx = threadIdx.x, ty = threadIdx.y;
#pragma unroll
    for (int i = 0; i < 4; i++)
        tile[ty + 8*i][tx] = prior[((size_t)b*T1_ + t1_0 + ty + 8*i)*T2_ + t2_0 + tx];
    __syncthreads();
#pragma unroll
    for (int i = 0; i < 4; i++)
        lpT[((size_t)b*T2_ + t2_0 + ty + 8*i)*T1_ + t1_0 + tx] =
            logf(tile[tx][ty + 8*i] + 1e-8f);
}

// fp32 conv kept for the CIN=512 first K layer only
template<int CIN, int KSZ, int PAD, int TLEN>
__global__ void __launch_bounds__(128) conv_lrelu(
        const float* __restrict__ x, const float* __restrict__ wgt,
        const float* __restrict__ bias, float* __restrict__ y)
{
    constexpr int TT  = 64;
    constexpr int CB  = 16;
    constexpr int INW = TT + 8;
    constexpr int WSLOT = (KSZ <= 4) ? 4 : 8;
    constexpr int OFF = 4 - PAD;
    __shared__ float sIn[CB][INW];
    __shared__ float sW[CB*HCH*WSLOT];

    const int b   = blockIdx.y;
    const int t0  = blockIdx.x * TT;
    const int tid = threadIdx.x;
    const int tg  = tid & 7;
    const int og  = tid >> 3;

    float acc[5][8];
#pragma unroll
    for (int i = 0; i < 5; i++)
#pragma unroll
        for (int j = 0; j < 8; j++) acc[i][j] = 0.f;

    for (int c0 = 0; c0 < CIN; c0 += CB) {
        for (int idx = tid; idx < CB*INW; idx += 128) {
            int ci = idx / INW, u = idx - ci*INW;
            int t = t0 + u - 4;
            sIn[ci][u] = ((unsigned)t < (unsigned)TLEN)
                       ? x[((size_t)b*CIN + c0 + ci)*TLEN + t] : 0.f;
        }
        for (int idx = tid; idx < CB*HCH*KSZ; idx += 128) {
            int ci  = idx / (HCH*KSZ);
            int rem = idx - ci*(HCH*KSZ);
            int oc  = rem / KSZ;
            int k   = rem - oc*KSZ;
            sW[(ci*HCH + oc)*WSLOT + k] =
                wgt[(size_t)oc*CIN*KSZ + (size_t)(c0 + ci)*KSZ + k];
        }
        __syncthreads();
#pragma unroll 1
        for (int ci = 0; ci < CB; ci++) {
            float wreg[16];
            float4 a0 = *(const float4*)&sIn[ci][tg*8 + 0];
            float4 a1 = *(const float4*)&sIn[ci][tg*8 + 4];
            float4 a2 = *(const float4*)&sIn[ci][tg*8 + 8];
            float4 a3 = *(const float4*)&sIn[ci][tg*8 + 12];
            wreg[0]=a0.x; wreg[1]=a0.y; wreg[2]=a0.z; wreg[3]=a0.w;
            wreg[4]=a1.x; wreg[5]=a1.y; wreg[6]=a1.z; wreg[7]=a1.w;
            wreg[8]=a2.x; wreg[9]=a2.y; wreg[10]=a2.z; wreg[11]=a2.w;
            wreg[12]=a3.x; wreg[13]=a3.y; wreg[14]=a3.z; wreg[15]=a3.w;
#pragma unroll
            for (int i = 0; i < 5; i++) {
                const float* wp = &sW[(ci*HCH + og*5 + i)*WSLOT];
                float wf[WSLOT];
                float4 b0 = *(const float4*)wp;
                wf[0]=b0.x; wf[1]=b0.y; wf[2]=b0.z; wf[3]=b0.w;
                if (WSLOT == 8) {
                    float4 b1 = *(const float4*)(wp + 4);
                    wf[4]=b1.x; wf[5]=b1.y; wf[6]=b1.z; wf[7]=b1.w;
                }
#pragma unroll
                for (int kk = 0; kk < KSZ; kk++)
#pragma unroll
                    for (int j = 0; j < 8; j++)
                        acc[i][j] = fmaf(wf[kk], wreg[j + kk + OFF], acc[i][j]);
            }
        }
        __syncthreads();
    }
#pragma unroll
    for (int i = 0; i < 5; i++) {
        int oc = og*5 + i;
        float bv = bias[oc];
        float4 o0, o1;
        float v;
        v = acc[i][0] + bv; o0.x = v >= 0.f ? v : SLOPE_*v;
        v = acc[i][1] + bv; o0.y = v >= 0.f ? v : SLOPE_*v;
        v = acc[i][2] + bv; o0.z = v >= 0.f ? v : SLOPE_*v;
        v = acc[i][3] + bv; o0.w = v >= 0.f ? v : SLOPE_*v;
        v = acc[i][4] + bv; o1.x = v >= 0.f ? v : SLOPE_*v;
        v = acc[i][5] + bv; o1.y = v >= 0.f ? v : SLOPE_*v;
        v = acc[i][6] + bv; o1.z = v >= 0.f ? v : SLOPE_*v;
        v = acc[i][7] + bv; o1.w = v >= 0.f ? v : SLOPE_*v;
        float* yp = &y[((size_t)b*HCH + oc)*TLEN + t0 + tg*8];
        *(float4*)yp       = o0;
        *(float4*)(yp + 4) = o1;
    }
}

template<int C, int T>
__global__ void __launch_bounds__(256) sumsq_kernel(
        const float* __restrict__ x, float* __restrict__ out)
{
    int idx = blockIdx.x * 256 + threadIdx.x;
    int b = idx / T, t = idx - b*T;
    float s = 0.f;
#pragma unroll 8
    for (int c = 0; c < C; c++) {
        float v = x[((size_t)b*C + c)*T + t];
        s = fmaf(v, v, s);
    }
    out[idx] = s;
}

__device__ __forceinline__ float blkMax(float v, float* sh) {
#pragma unroll
    for (int o = 16; o; o >>= 1) v = fmaxf(v, __shfl_xor_sync(0xffffffffu, v, o));
    if ((threadIdx.x & 31) == 0) sh[threadIdx.x >> 5] = v;
    __syncthreads();
    float r = sh[0];
#pragma unroll
    for (int i = 1; i < 8; i++) r = fmaxf(r, sh[i]);
    __syncthreads();
    return r;
}
__device__ __forceinline__ float blkSum(float v, float* sh) {
#pragma unroll
    for (int o = 16; o; o >>= 1) v += __shfl_xor_sync(0xffffffffu, v, o);
    if ((threadIdx.x & 31) == 0) sh[threadIdx.x >> 5] = v;
    __syncthreads();
    float r = sh[0];
#pragma unroll
    for (int i = 1; i < 8; i++) r += sh[i];
    __syncthreads();
    return r;
}

__global__ void __launch_bounds__(256) rowsoft_kernel(
        float* __restrict__ lp, float* __restrict__ lpT,
        float* __restrict__ soft)
{
    __shared__ float sh[8];
    const size_t off = (size_t)blockIdx.x * T1_;
    const int tid = threadIdx.x;
    float v0 = lp[off + tid], v1 = lp[off + 256 + tid];
    float m  = blkMax(fmaxf(v0, v1), sh);
    float s  = blkSum(__expf(v0 - m) + __expf(v1 - m), sh);
    float lse = m + __logf(s);
    float a0 = v0 - lse + lpT[off + tid];
    float a1 = v1 - lse + lpT[off + 256 + tid];
    float m2 = blkMax(fmaxf(a0, a1), sh);
    float p0 = expf(a0 - m2), p1 = expf(a1 - m2);
    float s2 = blkSum(p0 + p1, sh);
    float inv = 1.0f / s2;
    float sm0 = p0 * inv, sm1 = p1 * inv;
    lp[off + tid] = a0;            lp[off + 256 + tid] = a1;
    soft[off + tid] = sm0;         soft[off + 256 + tid] = sm1;
    lpT[off + tid] = logf(sm0);    lpT[off + 256 + tid] = logf(sm1);
}

__global__ void zero_kernel(float4* __restrict__ p) {
    size_t i = (size_t)blockIdx.x * blockDim.x + threadIdx.x;
    p[i] = make_float4(0.f, 0.f, 0.f, 0.f);
}

#define MAS_RING 8
#define MAS_SMEM (T2_*32*2 + T1_*4)

__global__ void __launch_bounds__(32) mas_kernel(
        const float* __restrict__ la, const int* __restrict__ enc_len,
        const int* __restrict__ dec_len, float* __restrict__ hard,
        float* __restrict__ dur)
{
    extern __shared__ unsigned short sBits[];
    int* durS = (int*)&sBits[T2_*32];
    const int b = blockIdx.x;
    const int lane = threadIdx.x;
    const int el = enc_len[b];
    const int dl = dec_len[b];
    const float* rowbase = la + (size_t)b*T2_*T1_ + lane*16;

    unsigned validbits = 0u;
    float logp[16];
#pragma unroll
    for (int k = 0; k < 16; k++) {
        logp[k] = (lane == 0 && k == 0) ? 0.f : NEGV;
        if (lane*16 + k < el) validbits |= (1u << k);
    }
    float4 ring[MAS_RING][4];
#pragma unroll
    for (int p = 0; p < MAS_RING; p++)
#pragma unroll
        for (int q = 0; q < 4; q++)
            ring[p][q] = *(const float4*)(rowbase + (size_t)p*T1_ + q*4);

    for (int t2b = 0; t2b < T2_; t2b += MAS_RING) {
#pragma unroll
        for (int u = 0; u < MAS_RING; u++) {
            const int t2 = t2b + u;
            float rv[16];
            rv[0]=ring[u][0].x;  rv[1]=ring[u][0].y;  rv[2]=ring[u][0].z;  rv[3]=ring[u][0].w;
            rv[4]=ring[u][1].x;  rv[5]=ring[u][1].y;  rv[6]=ring[u][1].z;  rv[7]=ring[u][1].w;
            rv[8]=ring[u][2].x;  rv[9]=ring[u][2].y;  rv[10]=ring[u][2].z; rv[11]=ring[u][2].w;
            rv[12]=ring[u][3].x; rv[13]=ring[u][3].y; rv[14]=ring[u][3].z; rv[15]=ring[u][3].w;
            const int tn = t2 + MAS_RING;
            if (tn < T2_) {
#pragma unroll
                for (int q = 0; q < 4; q++)
                    ring[u][q] = *(const float4*)(rowbase + (size_t)tn*T1_ + q*4);
            }
#pragma unroll
            for (int k = 0; k < 16; k++)
                rv[k] = ((validbits >> k) & 1u) ? rv[k] : NEGV;
            if (t2 == 0) {
#pragma unroll
                for (int k = 0; k < 16; k++)
                    if (lane > 0 || k > 0) rv[k] = NEGV;
            }
            float last = __shfl_up_sync(0xffffffffu, logp[15], 1);
            unsigned bits = 0u;
#pragma unroll
            for (int k = 15; k >= 0; k--) {
                float sh = (k == 0) ? last : logp[k-1];
                bool t1pos = (k > 0) || (lane > 0);
                bool take = t1pos && (sh >= logp[k]);
                float base = take ? sh : logp[k];
                if (take) bits |= (1u << k);
                logp[k] = rv[k] + base;
            }
            sBits[t2*32 + lane] = (unsigned short)bits;
        }
    }
    __syncwarp();
    for (int i = lane; i < T1_; i += 32) durS[i] = 0;
    __syncwarp();
    if (lane == 0) {
        int curr = el - 1;
        for (int i = T2_-1; i >= 0; --i) {
            if (i < dl) {
                hard[((size_t)b*T2_ + i)*T1_ + curr] = 1.0f;
                durS[curr]++;
                unsigned bits = sBits[i*32 + (curr >> 4)];
                curr -= (int)((bits >> (curr & 15)) & 1u);
            }
        }
    }
    __syncwarp();
    for (int i = lane; i < T1_; i += 32) dur[(size_t)b*T1_ + i] = (float)durS[i];
}

extern "C" void kernel_launch(void* const* d_in, const int* in_sizes, int n_in,
                              void* d_out, int out_size)
{
    const float* enc_in  = (const float*)d_in[0];
    const float* dec_in  = (const float*)d_in[1];
    const int*   enc_len = (const int*)d_in[2];
    const int*   dec_len = (const int*)d_in[3];
    const float* prior   = (const float*)d_in[5];
    const float* kw1 = (const float*)d_in[6];
    const float* kb1 = (const float*)d_in[7];
    const float* kw2 = (const float*)d_in[8];
    const float* kb2 = (const float*)d_in[9];
    const float* qw1 = (const float*)d_in[10];
    const float* qb1 = (const float*)d_in[11];
    const float* qw2 = (const float*)d_in[12];
    const float* qb2 = (const float*)d_in[13];
    const float* qw3 = (const float*)d_in[14];
    const float* qb3 = (const float*)d_in[15];

    float* outp = (float*)d_out;
    const size_t VOL = (size_t)B_*T2_*T1_;
    float* lp   = outp;
    float* soft = outp + VOL;
    float* hard = outp + 2*VOL;
    float* dur  = outp + 3*VOL;

    float *pK1, *pK, *pQA, *pQB, *pk2, *pq2, *plpT;
    cudaGetSymbolAddress((void**)&pK1,  g_K1);
    cudaGetSymbolAddress((void**)&pK,   g_K);
    cudaGetSymbolAddress((void**)&pQA,  g_QA);
    cudaGetSymbolAddress((void**)&pQB,  g_QB);
    cudaGetSymbolAddress((void**)&pk2,  g_k2);
    cudaGetSymbolAddress((void**)&pq2,  g_q2);
    cudaGetSymbolAddress((void**)&plpT, g_lpT);

    static int attrs_set = 0;
    if (!attrs_set) {
        cudaFuncSetAttribute(mas_kernel, cudaFuncAttributeMaxDynamicSharedMemorySize, MAS_SMEM);
        cudaFuncSetAttribute(attn_mma_kernel, cudaFuncAttributeMaxDynamicSharedMemorySize, ATTN_SMEM);
        cudaFuncSetAttribute(conv_mma_kernel<7,3,T2_>, cudaFuncAttributeMaxDynamicSharedMemorySize, CONV_SMEM);
        cudaFuncSetAttribute(conv_mma_kernel<3,1,T1_>, cudaFuncAttributeMaxDynamicSharedMemorySize, CONV_SMEM);
        attrs_set = 1;
    }

    transpose_logprior<<<dim3(T1_/32, T2_/32, B_), dim3(32, 8)>>>(prior, plpT);

    conv_lrelu<CENC, 3, 1, T1_><<<dim3(T1_/64, B_), 128>>>(enc_in, kw1, kb1, pK1);
    conv_mma_kernel<3,1,T1_><<<dim3(T1_/128, B_), 256, CONV_SMEM>>>(pK1, kw2, kb2, pK);
    conv_mma_kernel<7,3,T2_><<<dim3(T2_/128, B_), 256, CONV_SMEM>>>(dec_in, qw1, qb1, pQA);
    conv_mma_kernel<7,3,T2_><<<dim3(T2_/128, B_), 256, CONV_SMEM>>>(pQA, qw2, qb2, pQB);
    conv_mma_kernel<7,3,T2_><<<dim3(T2_/128, B_), 256, CONV_SMEM>>>(pQB, qw3, qb3, pQA);

    sumsq_kernel<HCH, T1_><<<B_*T1_/256, 256>>>(pK,  pk2);
    sumsq_kernel<HCH, T2_><<<B_*T2_/256, 256>>>(pQA, pq2);

    attn_mma_kernel<<<dim3(T2_/128, T1_/128, B_), 256, ATTN_SMEM>>>(pQA, pK, pq2, pk2, lp);
    rowsoft_kernel<<<B_*T2_, 256>>>(lp, plpT, soft);

    zero_kernel<<<(unsigned)(VOL/4/256), 256>>>((float4*)hard);

    mas_kernel<<<B_, 32, MAS_SMEM>>>(plpT, enc_len, dec_len, hard, dur);
}

// round 13
// speedup vs baseline: 1.4713x; 1.1390x over previous
#include <cuda_runtime.h>
#include <cuda_bf16.h>
#include <cstdint>
#include <cstddef>

#define B_    32
#define T1_   512
#define T2_   2048
#define CENC  512
#define HCH   80
#define SLOPE_ 0.3f
#define TEMP_  0.0005f
#define NEGV  -1000000000.0f

__device__ float g_K1[B_*HCH*T1_];
__device__ float g_K [B_*HCH*T1_];
__device__ float g_QA[B_*HCH*T2_];
__device__ float g_QB[B_*HCH*T2_];
__device__ float g_k2[B_*T1_];
__device__ float g_q2[B_*T2_];
__device__ float g_lpT[(size_t)B_*T2_*T1_];

// ---------------- mma.sync helpers (base sm_80+ ISA) -------------------------
__device__ __forceinline__ uint32_t smem_u32(const void* p) {
    uint32_t a;
    asm("{ .reg .u64 t; cvta.to.shared.u64 t, %1; cvt.u32.u64 %0, t; }" : "=r"(a) : "l"(p));
    return a;
}
__device__ __forceinline__ void ldmat4(uint32_t* r, uint32_t addr) {
    asm volatile("ldmatrix.sync.aligned.m8n8.x4.shared.b16 {%0,%1,%2,%3}, [%4];"
        : "=r"(r[0]), "=r"(r[1]), "=r"(r[2]), "=r"(r[3]) : "r"(addr));
}
__device__ __forceinline__ void ldmat2(uint32_t* r, uint32_t addr) {
    asm volatile("ldmatrix.sync.aligned.m8n8.x2.shared.b16 {%0,%1}, [%2];"
        : "=r"(r[0]), "=r"(r[1]) : "r"(addr));
}
__device__ __forceinline__ void mma16816(float* d, const uint32_t* a, const uint32_t* b) {
    asm volatile("mma.sync.aligned.m16n8k16.row.col.f32.bf16.bf16.f32 "
        "{%0,%1,%2,%3}, {%4,%5,%6,%7}, {%8,%9}, {%0,%1,%2,%3};"
        : "+f"(d[0]), "+f"(d[1]), "+f"(d[2]), "+f"(d[3])
        : "r"(a[0]), "r"(a[1]), "r"(a[2]), "r"(a[3]), "r"(b[0]), "r"(b[1]));
}
__device__ __forceinline__ void bf16split(float v, __nv_bfloat16& h, __nv_bfloat16& l) {
    h = __float2bfloat16(v);
    l = __float2bfloat16(v - __bfloat162float(h));
}
__device__ __forceinline__ void cp_async4(uint32_t dst, const float* src) {
    asm volatile("cp.async.ca.shared.global [%0], [%1], 4;" :: "r"(dst), "l"(src));
}

// =================== attn distance GEMM (validated round 9) =================
#define AT_STRIDE 88
#define AT_TILE   (128*AT_STRIDE*2)
#define SM_AH 0
#define SM_AL (SM_AH + AT_TILE)
#define SM_BH (SM_AL + AT_TILE)
#define SM_BL (SM_BH + AT_TILE)
#define SM_Q2 (SM_BL + AT_TILE)
#define SM_K2 (SM_Q2 + 512)
#define ATTN_SMEM (SM_K2 + 512)
#define SM_OUT 0
#define OUT_STRIDE 132

__global__ void __launch_bounds__(256) attn_mma_kernel(
        const float* __restrict__ Q, const float* __restrict__ K,
        const float* __restrict__ q2s, const float* __restrict__ k2s,
        float* __restrict__ outp)
{
    extern __shared__ char smem[];
    const uint32_t smb = smem_u32(smem);
    const int tid  = threadIdx.x;
    const int wid  = tid >> 5;
    const int lane = tid & 31;
    const int t2_0 = blockIdx.x * 128;
    const int t1_0 = blockIdx.y * 128;
    const int b    = blockIdx.z;

    for (int idx = tid; idx < HCH*128; idx += 256) {
        int c = idx >> 7, row = idx & 127;
        __nv_bfloat16 h, l;
        bf16split(Q[((size_t)b*HCH + c)*T2_ + t2_0 + row], h, l);
        *(__nv_bfloat16*)(smem + SM_AH + (row*AT_STRIDE + c)*2) = h;
        *(__nv_bfloat16*)(smem + SM_AL + (row*AT_STRIDE + c)*2) = l;
    }
    for (int idx = tid; idx < HCH*128; idx += 256) {
        int c = idx >> 7, row = idx & 127;
        __nv_bfloat16 h, l;
        bf16split(K[((size_t)b*HCH + c)*T1_ + t1_0 + row], h, l);
        *(__nv_bfloat16*)(smem + SM_BH + (row*AT_STRIDE + c)*2) = h;
        *(__nv_bfloat16*)(smem + SM_BL + (row*AT_STRIDE + c)*2) = l;
    }
    if (tid < 128) {
        *(float*)(smem + SM_Q2 + tid*4) = q2s[(size_t)b*T2_ + t2_0 + tid];
        *(float*)(smem + SM_K2 + tid*4) = k2s[(size_t)b*T1_ + t1_0 + tid];
    }
    __syncthreads();

    const int m_blk = (wid & 1) * 64;
    const int n_blk = (wid >> 1) * 32;

    float acc[4][4][4];
#pragma unroll
    for (int mi = 0; mi < 4; mi++)
#pragma unroll
        for (int ni = 0; ni < 4; ni++)
#pragma unroll
            for (int q = 0; q < 4; q++) acc[mi][ni][q] = 0.f;

    const uint32_t a_lrow = (uint32_t)(lane & 15);
    const uint32_t a_lcol = (uint32_t)((lane >> 4) << 3);
    const uint32_t b_lrow = (uint32_t)(lane & 7);
    const uint32_t b_lcol = (uint32_t)(((lane >> 3) & 1) << 3);

#pragma unroll
    for (int ks = 0; ks < 5; ks++) {
        const uint32_t kc = ks * 16;
        uint32_t Ah[4][4], Al[4][4], Bh[4][2], Bl[4][2];
#pragma unroll
        for (int mi = 0; mi < 4; mi++) {
            uint32_t off = ((m_blk + mi*16 + a_lrow)*AT_STRIDE + kc + a_lcol)*2;
            ldmat4(Ah[mi], smb + SM_AH + off);
            ldmat4(Al[mi], smb + SM_AL + off);
        }
#pragma unroll
        for (int ni = 0; ni < 4; ni++) {
            uint32_t off = ((n_blk + ni*8 + b_lrow)*AT_STRIDE + kc + b_lcol)*2;
            ldmat2(Bh[ni], smb + SM_BH + off);
            ldmat2(Bl[ni], smb + SM_BL + off);
        }
#pragma unroll
        for (int mi = 0; mi < 4; mi++)
#pragma unroll
            for (int ni = 0; ni < 4; ni++) {
                mma16816(acc[mi][ni], Ah[mi], Bh[ni]);
                mma16816(acc[mi][ni], Ah[mi], Bl[ni]);
                mma16816(acc[mi][ni], Al[mi], Bh[ni]);
            }
    }
    __syncthreads();

    const int gid = lane >> 2, tig = lane & 3;
    const float* sQ2 = (const float*)(smem + SM_Q2);
    const float* sK2 = (const float*)(smem + SM_K2);
#pragma unroll
    for (int mi = 0; mi < 4; mi++) {
        int r0 = m_blk + mi*16 + gid;
        int r1 = r0 + 8;
        float q20 = sQ2[r0], q21 = sQ2[r1];
#pragma unroll
        for (int ni = 0; ni < 4; ni++) {
            int c0 = n_blk + ni*8 + tig*2;
            float k20 = sK2[c0], k21 = sK2[c0 + 1];
            float2 lo, hi;
            lo.x = TEMP_*(2.f*acc[mi][ni][0] - q20 - k20);
            lo.y = TEMP_*(2.f*acc[mi][ni][1] - q20 - k21);
            hi.x = TEMP_*(2.f*acc[mi][ni][2] - q21 - k20);
            hi.y = TEMP_*(2.f*acc[mi][ni][3] - q21 - k21);
            *(float2*)(smem + SM_OUT + (r0*OUT_STRIDE + c0)*4) = lo;
            *(float2*)(smem + SM_OUT + (r1*OUT_STRIDE + c0)*4) = hi;
        }
    }
    __syncthreads();
#pragma unroll 4
    for (int it = 0; it < 16; it++) {
        int row = it*8 + (tid >> 5);
        float4 v = *(const float4*)(smem + SM_OUT + (row*OUT_STRIDE + lane*4)*4);
        *(float4*)&outp[((size_t)b*T2_ + t2_0 + row)*T1_ + t1_0 + lane*4] = v;
    }
}

// ====== conv (any CIN) as tap-shifted GEMM; cp.async W pipeline, 256-t tile ==
template<int KSZ, int PAD, int TLEN, int CIN>
struct CCfg {
    static constexpr int TT  = 256;
    static constexpr int CB  = (CIN == 80) ? 80 : 64;
    static constexpr int NCB = CIN / CB;
    static constexpr int CVS = CB + 8;
    static constexpr int XR  = TT + KSZ - 1;
    static constexpr int NKS = CB / 16;
    static constexpr int NJ  = NCB * KSZ;
    static constexpr int XHALF = XR * CVS * 2;
    static constexpr int RAWSZ = HCH * CB * 4;
    static constexpr int BFHALF = HCH * CVS * 2;
    static constexpr int O_XH = 0;
    static constexpr int O_XL = XHALF;
    static constexpr int O_R0 = 2*XHALF;
    static constexpr int O_R1 = O_R0 + RAWSZ;
    static constexpr int O_BH = O_R1 + RAWSZ;
    static constexpr int O_BL = O_BH + BFHALF;
    static constexpr int O_BIAS = O_BL + BFHALF;
    static constexpr int SMEM = O_BIAS + 512;
};
#define CV_TSTR 264

template<int KSZ, int PAD, int TLEN, int CIN>
__global__ void __launch_bounds__(512) conv_mma2(
        const float* __restrict__ x, const float* __restrict__ wgt,
        const float* __restrict__ bias, float* __restrict__ y)
{
    using C = CCfg<KSZ,PAD,TLEN,CIN>;
    extern __shared__ char smem[];
    const uint32_t smb = smem_u32(smem);
    const int tid  = threadIdx.x;
    const int wid  = tid >> 5;
    const int lane = tid & 31;
    const int t0   = blockIdx.x * 256;
    const int b    = blockIdx.y;

    if (tid < HCH) *(float*)(smem + C::O_BIAS + tid*4) = bias[tid];

    // prime cp.async for W(j=0) into raw buffer 0
    {
        uint32_t dst = smb + C::O_R0;
        for (int idx = tid; idx < HCH*C::CB; idx += 512) {
            int oc = idx / C::CB, ci = idx - oc*C::CB;
            cp_async4(dst + idx*4, wgt + ((size_t)oc*CIN + ci)*KSZ);
        }
        asm volatile("cp.async.commit_group;");
    }

    const int m_blk = (wid >> 1) * 32;
    const int n_blk = (wid & 1) * 40;

    float acc[2][5][4];
#pragma unroll
    for (int mi = 0; mi < 2; mi++)
#pragma unroll
        for (int ni = 0; ni < 5; ni++)
#pragma unroll
            for (int q = 0; q < 4; q++) acc[mi][ni][q] = 0.f;

    const uint32_t a_lrow = (uint32_t)(lane & 15);
    const uint32_t a_lcol = (uint32_t)((lane >> 4) << 3);
    const uint32_t b_lrow = (uint32_t)(lane & 7);
    const uint32_t b_lcol = (uint32_t)(((lane >> 3) & 1) << 3);

#pragma unroll 1
    for (int cb = 0; cb < C::NCB; cb++) {
        __syncthreads();   // X region free (all mma of previous cb done)
        for (int idx = tid; idx < C::CB*C::XR; idx += 512) {
            int c = idx / C::XR, r = idx - c*C::XR;
            int t = t0 + r - PAD;
            float v = ((unsigned)t < (unsigned)TLEN)
                    ? x[((size_t)b*CIN + cb*C::CB + c)*TLEN + t] : 0.f;
            __nv_bfloat16 h, l;
            bf16split(v, h, l);
            *(__nv_bfloat16*)(smem + C::O_XH + (r*C::CVS + c)*2) = h;
            *(__nv_bfloat16*)(smem + C::O_XL + (r*C::CVS + c)*2) = l;
        }
#pragma unroll 1
        for (int k = 0; k < KSZ; k++) {
            const int j = cb*KSZ + k;
            if (j + 1 < C::NJ) {
                int cb2 = (j+1) / KSZ, k2 = (j+1) - cb2*KSZ;
                uint32_t dst = smb + (((j+1) & 1) ? C::O_R1 : C::O_R0);
                for (int idx = tid; idx < HCH*C::CB; idx += 512) {
                    int oc = idx / C::CB, ci = idx - oc*C::CB;
                    cp_async4(dst + idx*4,
                              wgt + ((size_t)oc*CIN + cb2*C::CB + ci)*KSZ + k2);
                }
                asm volatile("cp.async.commit_group;");
                asm volatile("cp.async.wait_group 1;");
            } else {
                asm volatile("cp.async.wait_group 0;");
            }
            __syncthreads();   // raw[j&1] visible to all; prev mma done (bfW free); X visible
            {
                const float* rawp = (const float*)(smem + ((j & 1) ? C::O_R1 : C::O_R0));
                for (int idx = tid; idx < HCH*C::CB; idx += 512) {
                    int oc = idx / C::CB, ci = idx - oc*C::CB;
                    __nv_bfloat16 h, l;
                    bf16split(rawp[idx], h, l);
                    *(__nv_bfloat16*)(smem + C::O_BH + (oc*C::CVS + ci)*2) = h;
                    *(__nv_bfloat16*)(smem + C::O_BL + (oc*C::CVS + ci)*2) = l;
                }
            }
            __syncthreads();   // bfW ready
#pragma unroll
            for (int ks = 0; ks < C::NKS; ks++) {
                const uint32_t kc = ks * 16;
                uint32_t Ah[2][4], Al[2][4], Bh[5][2], Bl[5][2];
#pragma unroll
                for (int mi = 0; mi < 2; mi++) {
                    uint32_t off = ((uint32_t)(m_blk + mi*16 + k + a_lrow)*C::CVS + kc + a_lcol)*2;
                    ldmat4(Ah[mi], smb + C::O_XH + off);
                    ldmat4(Al[mi], smb + C::O_XL + off);
                }
#pragma unroll
                for (int ni = 0; ni < 5; ni++) {
                    uint32_t off = ((uint32_t)(n_blk + ni*8 + b_lrow)*C::CVS + kc + b_lcol)*2;
                    ldmat2(Bh[ni], smb + C::O_BH + off);
                    ldmat2(Bl[ni], smb + C::O_BL + off);
                }
#pragma unroll
                for (int mi = 0; mi < 2; mi++)
#pragma unroll
                    for (int ni = 0; ni < 5; ni++) {
                        mma16816(acc[mi][ni], Ah[mi], Bh[ni]);
                        mma16816(acc[mi][ni], Ah[mi], Bl[ni]);
                        mma16816(acc[mi][ni], Al[mi], Bh[ni]);
                    }
            }
        }
    }
    __syncthreads();   // done with X/W smem; bounce tile reuses it

    const int gid = lane >> 2, tig = lane & 3;
    const float* sB = (const float*)(smem + C::O_BIAS);
#pragma unroll
    for (int mi = 0; mi < 2; mi++) {
        int r0 = m_blk + mi*16 + gid;
        int r1 = r0 + 8;
#pragma unroll
        for (int ni = 0; ni < 5; ni++) {
            int c0 = n_blk + ni*8 + tig*2;
            float b0 = sB[c0], b1 = sB[c0+1];
            float v;
            v = acc[mi][ni][0] + b0; v = v >= 0.f ? v : SLOPE_*v;
            *(float*)(smem + (c0*CV_TSTR + r0)*4) = v;
            v = acc[mi][ni][1] + b1; v = v >= 0.f ? v : SLOPE_*v;
            *(float*)(smem + ((c0+1)*CV_TSTR + r0)*4) = v;
            v = acc[mi][ni][2] + b0; v = v >= 0.f ? v : SLOPE_*v;
            *(float*)(smem + (c0*CV_TSTR + r1)*4) = v;
            v = acc[mi][ni][3] + b1; v = v >= 0.f ? v : SLOPE_*v;
            *(float*)(smem + ((c0+1)*CV_TSTR + r1)*4) = v;
        }
    }
    __syncthreads();
    for (int idx = tid; idx < HCH*64; idx += 512) {
        int oc = idx >> 6, t4 = idx & 63;
        float4 v = *(const float4*)(smem + (oc*CV_TSTR + t4*4)*4);
        *(float4*)&y[((size_t)b*HCH + oc)*TLEN + t0 + t4*4] = v;
    }
}

// ---------------------------------------------------------------------------
__global__ void __launch_bounds__(256) transpose_logprior(
        const float* __restrict__ prior, float* __restrict__ lpT)
{
    __shared__ float tile[32][33];
    const int b = blockIdx.z;
    const int t1_0 = blockIdx.x * 32, t2_0 = blockIdx.y * 32;
    const int tx = threadIdx.x, ty = threadIdx.y;
#pragma unroll
    for (int i = 0; i < 4; i++)
        tile[ty + 8*i][tx] = prior[((size_t)b*T1_ + t1_0 + ty + 8*i)*T2_ + t2_0 + tx];
    __syncthreads();
#pragma unroll
    for (int i = 0; i < 4; i++)
        lpT[((size_t)b*T2_ + t2_0 + ty + 8*i)*T1_ + t1_0 + tx] =
            logf(tile[tx][ty + 8*i] + 1e-8f);
}

template<int C, int T>
__global__ void __launch_bounds__(256) sumsq_kernel(
        const float* __restrict__ x, float* __restrict__ out)
{
    int idx = blockIdx.x * 256 + threadIdx.x;
    int b = idx / T, t = idx - b*T;
    float s = 0.f;
#pragma unroll 8
    for (int c = 0; c < C; c++) {
        float v = x[((size_t)b*C + c)*T + t];
        s = fmaf(v, v, s);
    }
    out[idx] = s;
}

__device__ __forceinline__ float blkMax(float v, float* sh) {
#pragma unroll
    for (int o = 16; o; o >>= 1) v = fmaxf(v, __shfl_xor_sync(0xffffffffu, v, o));
    if ((threadIdx.x & 31) == 0) sh[threadIdx.x >> 5] = v;
    __syncthreads();
    float r = sh[0];
#pragma unroll
    for (int i = 1; i < 8; i++) r = fmaxf(r, sh[i]);
    __syncthreads();
    return r;
}
__device__ __forceinline__ float blkSum(float v, float* sh) {
#pragma unroll
    for (int o = 16; o; o >>= 1) v += __shfl_xor_sync(0xffffffffu, v, o);
    if ((threadIdx.x & 31) == 0) sh[threadIdx.x >> 5] = v;
    __syncthreads();
    float r = sh[0];
#pragma unroll
    for (int i = 1; i < 8; i++) r += sh[i];
    __syncthreads();
    return r;
}

__global__ void __launch_bounds__(256) rowsoft_kernel(
        float* __restrict__ lp, float* __restrict__ lpT,
        float* __restrict__ soft)
{
    __shared__ float sh[8];
    const size_t off = (size_t)blockIdx.x * T1_;
    const int tid = threadIdx.x;
    float v0 = lp[off + tid], v1 = lp[off + 256 + tid];
    float m  = blkMax(fmaxf(v0, v1), sh);
    float s  = blkSum(__expf(v0 - m) + __expf(v1 - m), sh);
    float lse = m + __logf(s);
    float a0 = v0 - lse + lpT[off + tid];
    float a1 = v1 - lse + lpT[off + 256 + tid];
    float m2 = blkMax(fmaxf(a0, a1), sh);
    float p0 = expf(a0 - m2), p1 = expf(a1 - m2);
    float s2 = blkSum(p0 + p1, sh);
    float inv = 1.0f / s2;
    float sm0 = p0 * inv, sm1 = p1 * inv;
    lp[off + tid] = a0;            lp[off + 256 + tid] = a1;
    soft[off + tid] = sm0;         soft[off + 256 + tid] = sm1;
    lpT[off + tid] = logf(sm0);    lpT[off + 256 + tid] = logf(sm1);
}

__global__ void zero_kernel(float4* __restrict__ p) {
    size_t i = (size_t)blockIdx.x * blockDim.x + threadIdx.x;
    p[i] = make_float4(0.f, 0.f, 0.f, 0.f);
}

#define MAS_RING 8
#define MAS_SMEM (T2_*32*2 + T1_*4)

__global__ void __launch_bounds__(32) mas_kernel(
        const float* __restrict__ la, const int* __restrict__ enc_len,
        const int* __restrict__ dec_len, float* __restrict__ hard,
        float* __restrict__ dur)
{
    extern __shared__ unsigned short sBits[];
    int* durS = (int*)&sBits[T2_*32];
    const int b = blockIdx.x;
    const int lane = threadIdx.x;
    const int el = enc_len[b];
    const int dl = dec_len[b];
    const float* rowbase = la + (size_t)b*T2_*T1_ + lane*16;

    unsigned validbits = 0u;
    float logp[16];
#pragma unroll
    for (int k = 0; k < 16; k++) {
        logp[k] = (lane == 0 && k == 0) ? 0.f : NEGV;
        if (lane*16 + k < el) validbits |= (1u << k);
    }
    float4 ring[MAS_RING][4];
#pragma unroll
    for (int p = 0; p < MAS_RING; p++)
#pragma unroll
        for (int q = 0; q < 4; q++)
            ring[p][q] = *(const float4*)(rowbase + (size_t)p*T1_ + q*4);

    for (int t2b = 0; t2b < T2_; t2b += MAS_RING) {
#pragma unroll
        for (int u = 0; u < MAS_RING; u++) {
            const int t2 = t2b + u;
            float rv[16];
            rv[0]=ring[u][0].x;  rv[1]=ring[u][0].y;  rv[2]=ring[u][0].z;  rv[3]=ring[u][0].w;
            rv[4]=ring[u][1].x;  rv[5]=ring[u][1].y;  rv[6]=ring[u][1].z;  rv[7]=ring[u][1].w;
            rv[8]=ring[u][2].x;  rv[9]=ring[u][2].y;  rv[10]=ring[u][2].z; rv[11]=ring[u][2].w;
            rv[12]=ring[u][3].x; rv[13]=ring[u][3].y; rv[14]=ring[u][3].z; rv[15]=ring[u][3].w;
            const int tn = t2 + MAS_RING;
            if (tn < T2_) {
#pragma unroll
                for (int q = 0; q < 4; q++)
                    ring[u][q] = *(const float4*)(rowbase + (size_t)tn*T1_ + q*4);
            }
#pragma unroll
            for (int k = 0; k < 16; k++)
                rv[k] = ((validbits >> k) & 1u) ? rv[k] : NEGV;
            if (t2 == 0) {
#pragma unroll
                for (int k = 0; k < 16; k++)
                    if (lane > 0 || k > 0) rv[k] = NEGV;
            }
            float last = __shfl_up_sync(0xffffffffu, logp[15], 1);
            unsigned bits = 0u;
#pragma unroll
            for (int k = 15; k >= 0; k--) {
                float sh = (k == 0) ? last : logp[k-1];
                bool t1pos = (k > 0) || (lane > 0);
                bool take = t1pos && (sh >= logp[k]);
                float base = take ? sh : logp[k];
                if (take) bits |= (1u << k);
                logp[k] = rv[k] + base;
            }
            sBits[t2*32 + lane] = (unsigned short)bits;
        }
    }
    __syncwarp();
    for (int i = lane; i < T1_; i += 32) durS[i] = 0;
    __syncwarp();
    if (lane == 0) {
        int curr = el - 1;
        for (int i = T2_-1; i >= 0; --i) {
            if (i < dl) {
                hard[((size_t)b*T2_ + i)*T1_ + curr] = 1.0f;
                durS[curr]++;
                unsigned bits = sBits[i*32 + (curr >> 4)];
                curr -= (int)((bits >> (curr & 15)) & 1u);
            }
        }
    }
    __syncwarp();
    for (int i = lane; i < T1_; i += 32) dur[(size_t)b*T1_ + i] = (float)durS[i];
}

extern "C" void kernel_launch(void* const* d_in, const int* in_sizes, int n_in,
                              void* d_out, int out_size)
{
    const float* enc_in  = (const float*)d_in[0];
    const float* dec_in  = (const float*)d_in[1];
    const int*   enc_len = (const int*)d_in[2];
    const int*   dec_len = (const int*)d_in[3];
    const float* prior   = (const float*)d_in[5];
    const float* kw1 = (const float*)d_in[6];
    const float* kb1 = (const float*)d_in[7];
    const float* kw2 = (const float*)d_in[8];
    const float* kb2 = (const float*)d_in[9];
    const float* qw1 = (const float*)d_in[10];
    const float* qb1 = (const float*)d_in[11];
    const float* qw2 = (const float*)d_in[12];
    const float* qb2 = (const float*)d_in[13];
    const float* qw3 = (const float*)d_in[14];
    const float* qb3 = (const float*)d_in[15];

    float* outp = (float*)d_out;
    const size_t VOL = (size_t)B_*T2_*T1_;
    float* lp   = outp;
    float* soft = outp + VOL;
    float* hard = outp + 2*VOL;
    float* dur  = outp + 3*VOL;

    float *pK1, *pK, *pQA, *pQB, *pk2, *pq2, *plpT;
    cudaGetSymbolAddress((void**)&pK1,  g_K1);
    cudaGetSymbolAddress((void**)&pK,   g_K);
    cudaGetSymbolAddress((void**)&pQA,  g_QA);
    cudaGetSymbolAddress((void**)&pQB,  g_QB);
    cudaGetSymbolAddress((void**)&pk2,  g_k2);
    cudaGetSymbolAddress((void**)&pq2,  g_q2);
    cudaGetSymbolAddress((void**)&plpT, g_lpT);

    static int attrs_set = 0;
    if (!attrs_set) {
        cudaFuncSetAttribute(mas_kernel, cudaFuncAttributeMaxDynamicSharedMemorySize, MAS_SMEM);
        cudaFuncSetAttribute(attn_mma_kernel, cudaFuncAttributeMaxDynamicSharedMemorySize, ATTN_SMEM);
        cudaFuncSetAttribute(conv_mma2<7,3,T2_,HCH>, cudaFuncAttributeMaxDynamicSharedMemorySize,
                             CCfg<7,3,T2_,HCH>::SMEM);
        cudaFuncSetAttribute(conv_mma2<3,1,T1_,HCH>, cudaFuncAttributeMaxDynamicSharedMemorySize,
                             CCfg<3,1,T1_,HCH>::SMEM);
        cudaFuncSetAttribute(conv_mma2<3,1,T1_,CENC>, cudaFuncAttributeMaxDynamicSharedMemorySize,
                             CCfg<3,1,T1_,CENC>::SMEM);
        attrs_set = 1;
    }

    transpose_logprior<<<dim3(T1_/32, T2_/32, B_), dim3(32, 8)>>>(prior, plpT);

    conv_mma2<3,1,T1_,CENC><<<dim3(T1_/256, B_), 512, CCfg<3,1,T1_,CENC>::SMEM>>>(enc_in, kw1, kb1, pK1);
    conv_mma2<3,1,T1_,HCH> <<<dim3(T1_/256, B_), 512, CCfg<3,1,T1_,HCH>::SMEM>>>(pK1, kw2, kb2, pK);
    conv_mma2<7,3,T2_,HCH> <<<dim3(T2_/256, B_), 512, CCfg<7,3,T2_,HCH>::SMEM>>>(dec_in, qw1, qb1, pQA);
    conv_mma2<7,3,T2_,HCH> <<<dim3(T2_/256, B_), 512, CCfg<7,3,T2_,HCH>::SMEM>>>(pQA, qw2, qb2, pQB);
    conv_mma2<7,3,T2_,HCH> <<<dim3(T2_/256, B_), 512, CCfg<7,3,T2_,HCH>::SMEM>>>(pQB, qw3, qb3, pQA);

    sumsq_kernel<HCH, T1_><<<B_*T1_/256, 256>>>(pK,  pk2);
    sumsq_kernel<HCH, T2_><<<B_*T2_/256, 256>>>(pQA, pq2);

    attn_mma_kernel<<<dim3(T2_/128, T1_/128, B_), 256, ATTN_SMEM>>>(pQA, pK, pq2, pk2, lp);
    rowsoft_kernel<<<B_*T2_, 256>>>(lp, plpT, soft);

    zero_kernel<<<(unsigned)(VOL/4/256), 256>>>((float4*)hard);

    mas_kernel<<<B_, 32, MAS_SMEM>>>(plpT, enc_len, dec_len, hard, dur);
}